// round 9
// baseline (speedup 1.0000x reference)
#include <cuda_runtime.h>
#include <math.h>
#include <stdint.h>

#define B_ 4
#define S_ 2048
#define D_ 2048
#define H_ 16
#define HD_ 128
#define E_ 6144
#define BS_ 8192
#define EPS_ 1.1920929e-07f

__device__ float g_qkv[(size_t)BS_ * E_];
__device__ float g_att[(size_t)BS_ * D_];
__device__ float g_xr [(size_t)BS_ * D_];
__device__ float g_wir[(size_t)E_  * D_];
__device__ float g_wor[(size_t)D_  * D_];
__device__ float g_qf [(size_t)64 * S_ * HD_];    // [bh][s][128] k-interleaved
__device__ float g_kf [(size_t)64 * S_ * HD_];    // [bh][s][128] k-interleaved
__device__ float2 g_vf [(size_t)64 * 1024 * HD_]; // [bh][pair-row][d] = (V[s],V[s+4])
__device__ float g_m2[1];

__device__ __forceinline__ unsigned tf32_of(float x) {
    unsigned r; asm("cvt.rna.tf32.f32 %0, %1;" : "=r"(r) : "f"(x)); return r;
}
__device__ __forceinline__ float tf32f(float x) { return __uint_as_float(tf32_of(x)); }
__device__ __forceinline__ float ex2f(float x) {
    float r; asm("ex2.approx.f32 %0, %1;" : "=f"(r) : "f"(x)); return r;
}
__device__ __forceinline__ void mma_tf32(float& c0, float& c1, float& c2, float& c3,
                                         unsigned a0, unsigned a1, unsigned a2, unsigned a3,
                                         unsigned b0, unsigned b1) {
    asm volatile("mma.sync.aligned.m16n8k8.row.col.f32.tf32.tf32.f32 "
        "{%0,%1,%2,%3}, {%4,%5,%6,%7}, {%8,%9}, {%0,%1,%2,%3};\n"
        : "+f"(c0), "+f"(c1), "+f"(c2), "+f"(c3)
        : "r"(a0), "r"(a1), "r"(a2), "r"(a3), "r"(b0), "r"(b1));
}
__device__ __forceinline__ void cp_async16(void* sdst, const void* gsrc) {
    unsigned s = (unsigned)__cvta_generic_to_shared(sdst);
    asm volatile("cp.async.cg.shared.global [%0], [%1], 16;\n" :: "r"(s), "l"(gsrc));
}
__device__ __forceinline__ void cp_commit() { asm volatile("cp.async.commit_group;\n"); }
__device__ __forceinline__ void cp_wait0() { asm volatile("cp.async.wait_group 0;\n"); }
__device__ __forceinline__ void cp_wait1() { asm volatile("cp.async.wait_group 1;\n"); }

// ---------------------------------------------------------------------------
__global__ void round_tf32(const float* __restrict__ src, float* __restrict__ dst, int n4)
{
    int i = blockIdx.x * blockDim.x + threadIdx.x;
    int st = gridDim.x * blockDim.x;
    for (; i < n4; i += st) {
        float4 v = reinterpret_cast<const float4*>(src)[i];
        v.x = tf32f(v.x); v.y = tf32f(v.y); v.z = tf32f(v.z); v.w = tf32f(v.w);
        reinterpret_cast<float4*>(dst)[i] = v;
    }
}

__global__ void gmax_kernel(const float* __restrict__ qg, const float* __restrict__ kg,
                            float* __restrict__ o)
{
    int t = threadIdx.x;
    float mq = 0.f, mk = 0.f;
#pragma unroll
    for (int i = 0; i < 4; i++) {
        mq = fmaxf(mq, fabsf(qg[t + i * 32]));
        mk = fmaxf(mk, fabsf(kg[t + i * 32]));
    }
#pragma unroll
    for (int s = 16; s; s >>= 1) {
        mq = fmaxf(mq, __shfl_xor_sync(0xffffffffu, mq, s));
        mk = fmaxf(mk, __shfl_xor_sync(0xffffffffu, mk, s));
    }
    if (t == 0) o[0] = 16.32253f * mq * mk * 1.002f + 0.01f;
}

// V pair repack (values already tf32-rounded by gemm1 epilogue)
__global__ void vpack_pairs(const float* __restrict__ qkv, float2* __restrict__ vf)
{
    int idx = blockIdx.x * blockDim.x + threadIdx.x;   // 64*1024*128
    int d  = idx & 127;
    int pr = (idx >> 7) & 1023;
    int bh = idx >> 17;
    int b = bh >> 4, h = bh & 15;
    int s_lo = (pr >> 2) * 8 + (pr & 3);
    const float* base = qkv + (size_t)(b * S_ + s_lo) * E_ + 2 * D_ + h * HD_ + d;
    vf[idx] = make_float2(base[0], base[(size_t)4 * E_]);
}

// ---------------------------------------------------------------------------
// TF32 GEMM (identical to R4 known-good)
// ---------------------------------------------------------------------------
#define GLD 20
#define GST (128 * GLD)
template<bool ROUND>
__global__ __launch_bounds__(128, 2) void gemm_tf32_v2(
    const float* __restrict__ A, const float* __restrict__ W,
    float* __restrict__ C, int M, int N, int K)
{
    extern __shared__ float smem[];
    float* sA = smem;
    float* sB = smem + 3 * GST;
    const int t = threadIdx.x, warp = t >> 5, lane = t & 31;
    const int g = lane >> 2, tq = lane & 3, wy = warp >> 1, wx = warp & 1;
    const int m0 = blockIdx.y * 128, n0 = blockIdx.x * 128;
    const int lrow = t >> 2, lkq = t & 3;
    const float* Ab = A + (size_t)m0 * K;
    const float* Wb = W + (size_t)n0 * K;
    float acc[4][8][4];
#pragma unroll
    for (int i = 0; i < 4; i++)
#pragma unroll
        for (int j = 0; j < 8; j++)
#pragma unroll
            for (int r = 0; r < 4; r++) acc[i][j][r] = 0.f;
    auto issue = [&](int kc, int st) {
        int k0 = kc * 16;
#pragma unroll
        for (int u = 0; u < 4; u++) {
            int row = lrow + u * 32;
            cp_async16(&sA[st * GST + row * GLD + lkq * 4], Ab + (size_t)row * K + k0 + lkq * 4);
        }
#pragma unroll
        for (int u = 0; u < 4; u++) {
            int row = lrow + u * 32;
            cp_async16(&sB[st * GST + row * GLD + lkq * 4], Wb + (size_t)row * K + k0 + lkq * 4);
        }
        cp_commit();
    };
    const int nk = K / 16;
    issue(0, 0); issue(1, 1);
    for (int kc = 0; kc < nk; kc++) {
        if (kc + 1 < nk) cp_wait1(); else cp_wait0();
        __syncthreads();
        if (kc + 2 < nk) issue(kc + 2, (kc + 2) % 3);
        const float* cA = &sA[(kc % 3) * GST];
        const float* cB = &sB[(kc % 3) * GST];
#pragma unroll
        for (int ks = 0; ks < 2; ks++) {
            unsigned af[4][4];
#pragma unroll
            for (int mt = 0; mt < 4; mt++) {
                const float* base = &cA[(wy * 64 + mt * 16 + g) * GLD + ks * 8 + tq];
                af[mt][0] = __float_as_uint(base[0]);
                af[mt][1] = __float_as_uint(base[8 * GLD]);
                af[mt][2] = __float_as_uint(base[4]);
                af[mt][3] = __float_as_uint(base[8 * GLD + 4]);
            }
            unsigned bf[8][2];
#pragma unroll
            for (int nt = 0; nt < 8; nt++) {
                const float* base = &cB[(wx * 64 + nt * 8 + g) * GLD + ks * 8 + tq];
                bf[nt][0] = __float_as_uint(base[0]);
                bf[nt][1] = __float_as_uint(base[4]);
            }
#pragma unroll
            for (int mt = 0; mt < 4; mt++)
#pragma unroll
                for (int nt = 0; nt < 8; nt++)
                    mma_tf32(acc[mt][nt][0], acc[mt][nt][1], acc[mt][nt][2], acc[mt][nt][3],
                             af[mt][0], af[mt][1], af[mt][2], af[mt][3], bf[nt][0], bf[nt][1]);
        }
    }
#pragma unroll
    for (int mt = 0; mt < 4; mt++) {
        int r0 = m0 + wy * 64 + mt * 16 + g;
#pragma unroll
        for (int nt = 0; nt < 8; nt++) {
            int col = n0 + wx * 64 + nt * 8 + tq * 2;
            float c0 = acc[mt][nt][0], c1 = acc[mt][nt][1];
            float c2 = acc[mt][nt][2], c3 = acc[mt][nt][3];
            if (ROUND) { c0 = tf32f(c0); c1 = tf32f(c1); c2 = tf32f(c2); c3 = tf32f(c3); }
            *reinterpret_cast<float2*>(C + (size_t)r0 * N + col)       = make_float2(c0, c1);
            *reinterpret_cast<float2*>(C + (size_t)(r0 + 8) * N + col) = make_float2(c2, c3);
        }
    }
}

// ---------------------------------------------------------------------------
// RMSNorm q/k -> compact head-major, k-pair-interleaved buffers (tf32-rounded).
// Within each 8-k group, f32 stored at newpos = (k&3)*2 + (k>>2 & 1).
// ---------------------------------------------------------------------------
__global__ void rmsnorm_pack(const float* __restrict__ qkv,
                             const float* __restrict__ qg, const float* __restrict__ kg,
                             float* __restrict__ qf, float* __restrict__ kf)
{
    int warp = (blockIdx.x * blockDim.x + threadIdx.x) >> 5;
    int lane = threadIdx.x & 31;
    const int half = B_ * S_ * H_;
    int part = warp / half;
    int rem  = warp % half;
    int bs   = rem / H_;
    int h    = rem % H_;
    int b    = bs >> 11, s = bs & 2047;
    const float* p = qkv + (size_t)bs * E_ + part * D_ + h * HD_;
    float4 v = *reinterpret_cast<const float4*>(p + lane * 4);
    float ss = v.x*v.x + v.y*v.y + v.z*v.z + v.w*v.w;
#pragma unroll
    for (int o = 16; o; o >>= 1) ss += __shfl_xor_sync(0xffffffffu, ss, o);
    float sc = rsqrtf(ss * (1.0f / 128.0f) + EPS_);
    const float* gam = part ? kg : qg;
    float4 gv = *reinterpret_cast<const float4*>(gam + lane * 4);
    float o0 = tf32f(v.x * sc * gv.x);
    float o1 = tf32f(v.y * sc * gv.y);
    float o2 = tf32f(v.z * sc * gv.z);
    float o3 = tf32f(v.w * sc * gv.w);
    float* dst = (part ? kf : qf) + ((size_t)((b * 16 + h) * S_ + s)) * HD_
               + (lane >> 1) * 8 + (lane & 1);
    dst[0] = o0; dst[2] = o1; dst[4] = o2; dst[6] = o3;
}

// ---------------------------------------------------------------------------
// Causal flash attention v5: tf32 MMA, fixed-max softmax, pair-interleaved
// LDS.64 frags, compact gmem buffers, 2-stage cp.async ring, occ 3.
// 128 thr = 4 warps, BQ=64, BKV=32.
// ---------------------------------------------------------------------------
#define KSTRIDE 136                 // f32 per K row (128 + 8), 8B-stride 68 (mod16=4)
#define VSTRIDE 264                 // f32 per V pair-row (256 + 8), 8B-stride 132 (mod16=4)
#define KSTB (32 * KSTRIDE * 4)     // 17408 B
#define VSTB (16 * VSTRIDE * 4)     // 16896 B
#define STAGEB (KSTB + VSTB)        // 34304 B

__global__ __launch_bounds__(128, 3) void attn_v5(
    const float* __restrict__ qf_g, const float* __restrict__ kf_g,
    const float2* __restrict__ vf_g, const float* __restrict__ m2p,
    float* __restrict__ out)
{
    extern __shared__ __align__(16) char smc[];

    const int t    = threadIdx.x;
    const int w    = t >> 5;
    const int lane = t & 31;
    const int g    = lane >> 2;
    const int tq   = lane & 3;

    const int bh   = blockIdx.x >> 5;
    const int qblk = 31 - (blockIdx.x & 31);
    const int b    = bh >> 4;
    const int h    = bh & 15;

    const int q0  = qblk * 64;
    const int qg0 = q0 + w * 16 + g;
    const int qg1 = qg0 + 8;
    const float M2 = m2p[0];

    const float*  qb = qf_g + (size_t)bh * S_ * HD_;
    const char*   kb = (const char*)(kf_g + (size_t)bh * S_ * HD_);
    const char*   vb = (const char*)(vf_g + (size_t)bh * 1024 * HD_);

    // Q frags (interleaved layout: k=ks*8+tq at f32 offset ks*8+tq*2, k+4 at +1)
    unsigned qf[16][4];
#pragma unroll
    for (int ks = 0; ks < 16; ks++) {
        float2 lo = *reinterpret_cast<const float2*>(qb + (size_t)qg0 * HD_ + ks * 8 + tq * 2);
        float2 hi = *reinterpret_cast<const float2*>(qb + (size_t)qg1 * HD_ + ks * 8 + tq * 2);
        qf[ks][0] = __float_as_uint(lo.x);
        qf[ks][2] = __float_as_uint(lo.y);
        qf[ks][1] = __float_as_uint(hi.x);
        qf[ks][3] = __float_as_uint(hi.y);
    }

    float acc[16][4];
#pragma unroll
    for (int i = 0; i < 16; i++)
#pragma unroll
        for (int r = 0; r < 4; r++) acc[i][r] = 0.f;
    float l0 = 0.f, l1 = 0.f;
    const float sc2 = 0.08838834764831845f * 1.4426950408889634f;

    auto issue = [&](int j, int st) {
        char* kdst = smc + st * STAGEB;
        char* vdst = kdst + KSTB;
        const char* ksrc = kb + (size_t)j * 32 * 512;      // 32 rows x 512B
        const char* vsrc = vb + (size_t)(j * 16) * 1024;   // 16 pair-rows x 1024B
#pragma unroll
        for (int u = 0; u < 8; u++) {
            int c = u * 128 + t;
            int r = c >> 5, col = c & 31;
            cp_async16(kdst + r * (KSTRIDE * 4) + col * 16, ksrc + r * 512 + col * 16);
        }
#pragma unroll
        for (int u = 0; u < 8; u++) {
            int c = u * 128 + t;
            int r = c >> 6, col = c & 63;
            cp_async16(vdst + r * (VSTRIDE * 4) + col * 16, vsrc + r * 1024 + col * 16);
        }
        cp_commit();
    };

    const int nblk = 2 * qblk + 2;
    issue(0, 0);

    const int src0 = (lane & ~3) | (tq >> 1);
    const int src1 = src0 + 2;
    const bool odd = (tq & 1);

    for (int j = 0; j < nblk; j++) {
        cp_wait0();
        __syncthreads();
        if (j + 1 < nblk) issue(j + 1, (j + 1) & 1);

        const float* cK = (const float*)(smc + (j & 1) * STAGEB);
        const float* cV = (const float*)(smc + (j & 1) * STAGEB + KSTB);
        const int k0 = j * 32;

        // ---- S = Q K^T (m16 x n32, k=128) ----
        float sa[4][4];
#pragma unroll
        for (int nt = 0; nt < 4; nt++)
#pragma unroll
            for (int r = 0; r < 4; r++) sa[nt][r] = 0.f;
#pragma unroll
        for (int ks = 0; ks < 16; ks++) {
#pragma unroll
            for (int nt = 0; nt < 4; nt++) {
                float2 bp = *reinterpret_cast<const float2*>(
                    &cK[(nt * 8 + g) * KSTRIDE + ks * 8 + tq * 2]);
                mma_tf32(sa[nt][0], sa[nt][1], sa[nt][2], sa[nt][3],
                         qf[ks][0], qf[ks][1], qf[ks][2], qf[ks][3],
                         __float_as_uint(bp.x), __float_as_uint(bp.y));
            }
        }

        // ---- fixed-max softmax: p = 2^(s*sc2 - M2), masked -> 0 ----
        if (k0 + 31 > q0 + w * 16) {
#pragma unroll
            for (int nt = 0; nt < 4; nt++) {
                int kva = k0 + nt * 8 + tq * 2;
                float p0 = ex2f(fmaf(sa[nt][0], sc2, -M2));
                float p1 = ex2f(fmaf(sa[nt][1], sc2, -M2));
                float p2 = ex2f(fmaf(sa[nt][2], sc2, -M2));
                float p3 = ex2f(fmaf(sa[nt][3], sc2, -M2));
                p0 = (kva     <= qg0) ? p0 : 0.f;
                p1 = (kva + 1 <= qg0) ? p1 : 0.f;
                p2 = (kva     <= qg1) ? p2 : 0.f;
                p3 = (kva + 1 <= qg1) ? p3 : 0.f;
                l0 += p0 + p1; l1 += p2 + p3;
                sa[nt][0] = tf32f(p0); sa[nt][1] = tf32f(p1);
                sa[nt][2] = tf32f(p2); sa[nt][3] = tf32f(p3);
            }
        } else {
#pragma unroll
            for (int nt = 0; nt < 4; nt++) {
                float p0 = ex2f(fmaf(sa[nt][0], sc2, -M2));
                float p1 = ex2f(fmaf(sa[nt][1], sc2, -M2));
                float p2 = ex2f(fmaf(sa[nt][2], sc2, -M2));
                float p3 = ex2f(fmaf(sa[nt][3], sc2, -M2));
                l0 += p0 + p1; l1 += p2 + p3;
                sa[nt][0] = tf32f(p0); sa[nt][1] = tf32f(p1);
                sa[nt][2] = tf32f(p2); sa[nt][3] = tf32f(p3);
            }
        }

        // ---- PV: A-frags via quad shuffles, B-frags via paired LDS.64 ----
#pragma unroll
        for (int ks = 0; ks < 4; ks++) {
            float e0 = __shfl_sync(0xffffffffu, sa[ks][0], src0);
            float e1 = __shfl_sync(0xffffffffu, sa[ks][1], src0);
            float f0 = __shfl_sync(0xffffffffu, sa[ks][0], src1);
            float f1 = __shfl_sync(0xffffffffu, sa[ks][1], src1);
            float e2 = __shfl_sync(0xffffffffu, sa[ks][2], src0);
            float e3 = __shfl_sync(0xffffffffu, sa[ks][3], src0);
            float f2 = __shfl_sync(0xffffffffu, sa[ks][2], src1);
            float f3 = __shfl_sync(0xffffffffu, sa[ks][3], src1);
            unsigned a0 = __float_as_uint(odd ? e1 : e0);
            unsigned a2 = __float_as_uint(odd ? f1 : f0);
            unsigned a1 = __float_as_uint(odd ? e3 : e2);
            unsigned a3 = __float_as_uint(odd ? f3 : f2);
            const float* vr = &cV[(ks * 4 + tq) * VSTRIDE];
#pragma unroll
            for (int nt = 0; nt < 16; nt++) {
                float2 bp = *reinterpret_cast<const float2*>(vr + (nt * 8 + g) * 2);
                mma_tf32(acc[nt][0], acc[nt][1], acc[nt][2], acc[nt][3],
                         a0, a1, a2, a3,
                         __float_as_uint(bp.x), __float_as_uint(bp.y));
            }
        }
    }

    l0 += __shfl_xor_sync(0xffffffffu, l0, 1);
    l0 += __shfl_xor_sync(0xffffffffu, l0, 2);
    l1 += __shfl_xor_sync(0xffffffffu, l1, 1);
    l1 += __shfl_xor_sync(0xffffffffu, l1, 2);

    float inv0 = 1.0f / l0, inv1 = 1.0f / l1;
    float* o0 = out + (size_t)(b * S_ + qg0) * D_ + h * HD_;
    float* o1 = out + (size_t)(b * S_ + qg1) * D_ + h * HD_;
#pragma unroll
    for (int nt = 0; nt < 16; nt++) {
        int d = nt * 8 + tq * 2;
        *reinterpret_cast<float2*>(o0 + d) =
            make_float2(tf32f(acc[nt][0] * inv0), tf32f(acc[nt][1] * inv0));
        *reinterpret_cast<float2*>(o1 + d) =
            make_float2(tf32f(acc[nt][2] * inv1), tf32f(acc[nt][3] * inv1));
    }
}

// ---------------------------------------------------------------------------
extern "C" void kernel_launch(void* const* d_in, const int* in_sizes, int n_in,
                              void* d_out, int out_size)
{
    const float* x     = (const float*)d_in[0];
    const float* w_in  = (const float*)d_in[1];
    const float* w_out = (const float*)d_in[2];
    const float* qg    = (const float*)d_in[3];
    const float* kg    = (const float*)d_in[4];
    float* out = (float*)d_out;

    float *qkv, *att, *xr, *wir, *wor, *m2, *qf, *kf;
    float2* vf;
    cudaGetSymbolAddress((void**)&qkv, g_qkv);
    cudaGetSymbolAddress((void**)&att, g_att);
    cudaGetSymbolAddress((void**)&xr,  g_xr);
    cudaGetSymbolAddress((void**)&wir, g_wir);
    cudaGetSymbolAddress((void**)&wor, g_wor);
    cudaGetSymbolAddress((void**)&m2,  g_m2);
    cudaGetSymbolAddress((void**)&qf,  g_qf);
    cudaGetSymbolAddress((void**)&kf,  g_kf);
    cudaGetSymbolAddress((void**)&vf,  g_vf);

    round_tf32<<<1184, 256>>>(x,     xr,  BS_ * D_ / 4);
    round_tf32<<<1184, 256>>>(w_in,  wir, E_  * D_ / 4);
    round_tf32<<<1184, 256>>>(w_out, wor, D_  * D_ / 4);
    gmax_kernel<<<1, 32>>>(qg, kg, m2);

    const int gsm = 6 * GST * 4;
    cudaFuncSetAttribute(gemm_tf32_v2<true>,  cudaFuncAttributeMaxDynamicSharedMemorySize, gsm);
    cudaFuncSetAttribute(gemm_tf32_v2<false>, cudaFuncAttributeMaxDynamicSharedMemorySize, gsm);

    // 1) QKV projection (tf32, rounded epilogue)
    gemm_tf32_v2<true><<<dim3(E_ / 128, BS_ / 128), 128, gsm>>>(xr, wir, qkv, BS_, E_, D_);

    // 2) RMSNorm q/k -> compact interleaved buffers; V -> pair buffer
    rmsnorm_pack<<<32768, 256>>>(qkv, qg, kg, qf, kf);
    vpack_pairs<<<64 * 1024 * 128 / 256, 256>>>(qkv, vf);

    // 3) tf32 attention (fixed-max softmax), occ 3
    const int asm_ = 2 * STAGEB;   // 68608 B
    cudaFuncSetAttribute(attn_v5, cudaFuncAttributeMaxDynamicSharedMemorySize, asm_);
    attn_v5<<<64 * 32, 128, asm_>>>(qf, kf, vf, m2, att);

    // 4) output projection (tf32)
    gemm_tf32_v2<false><<<dim3(D_ / 128, BS_ / 128), 128, gsm>>>(att, wor, out, BS_, D_, D_);
}

// round 10
// speedup vs baseline: 1.0033x; 1.0033x over previous
#include <cuda_runtime.h>
#include <math.h>
#include <stdint.h>

#define B_ 4
#define S_ 2048
#define D_ 2048
#define H_ 16
#define HD_ 128
#define E_ 6144
#define BS_ 8192
#define EPS_ 1.1920929e-07f

__device__ float g_qkv[(size_t)BS_ * E_];
__device__ float g_att[(size_t)BS_ * D_];
__device__ float g_xr [(size_t)BS_ * D_];
__device__ float g_wir[(size_t)E_  * D_];
__device__ float g_wor[(size_t)D_  * D_];
__device__ float g_qf [(size_t)64 * S_ * HD_];    // [bh][s][128] k-interleaved
__device__ float g_kf [(size_t)64 * S_ * HD_];    // [bh][s][128] k-interleaved
__device__ float2 g_vf [(size_t)64 * 1024 * HD_]; // [bh][pair-row][d] = (V[s],V[s+4])
__device__ float g_m2[1];

__device__ __forceinline__ unsigned tf32_of(float x) {
    unsigned r; asm("cvt.rna.tf32.f32 %0, %1;" : "=r"(r) : "f"(x)); return r;
}
__device__ __forceinline__ float tf32f(float x) { return __uint_as_float(tf32_of(x)); }
__device__ __forceinline__ float ex2f(float x) {
    float r; asm("ex2.approx.f32 %0, %1;" : "=f"(r) : "f"(x)); return r;
}
__device__ __forceinline__ void mma_tf32(float& c0, float& c1, float& c2, float& c3,
                                         unsigned a0, unsigned a1, unsigned a2, unsigned a3,
                                         unsigned b0, unsigned b1) {
    asm volatile("mma.sync.aligned.m16n8k8.row.col.f32.tf32.tf32.f32 "
        "{%0,%1,%2,%3}, {%4,%5,%6,%7}, {%8,%9}, {%0,%1,%2,%3};\n"
        : "+f"(c0), "+f"(c1), "+f"(c2), "+f"(c3)
        : "r"(a0), "r"(a1), "r"(a2), "r"(a3), "r"(b0), "r"(b1));
}
__device__ __forceinline__ void cp_async16(void* sdst, const void* gsrc) {
    unsigned s = (unsigned)__cvta_generic_to_shared(sdst);
    asm volatile("cp.async.cg.shared.global [%0], [%1], 16;\n" :: "r"(s), "l"(gsrc));
}
__device__ __forceinline__ void cp_commit() { asm volatile("cp.async.commit_group;\n"); }
__device__ __forceinline__ void cp_wait0() { asm volatile("cp.async.wait_group 0;\n"); }
__device__ __forceinline__ void cp_wait1() { asm volatile("cp.async.wait_group 1;\n"); }

// ---------------------------------------------------------------------------
// Fused prepass: tf32-round x/w_in/w_out (segmented grid-stride) + gmax (blk 0)
// ---------------------------------------------------------------------------
#define N0_ (BS_ * D_ / 4)
#define N1_ (E_ * D_ / 4)
#define N2_ (D_ * D_ / 4)

__global__ void prep_all(const float* __restrict__ x, const float* __restrict__ wi,
                         const float* __restrict__ wo,
                         float* __restrict__ xr, float* __restrict__ wir,
                         float* __restrict__ wor,
                         const float* __restrict__ qg, const float* __restrict__ kg,
                         float* __restrict__ m2)
{
    if (blockIdx.x == 0 && threadIdx.x < 32) {
        int t = threadIdx.x;
        float mq = 0.f, mk = 0.f;
#pragma unroll
        for (int i = 0; i < 4; i++) {
            mq = fmaxf(mq, fabsf(qg[t + i * 32]));
            mk = fmaxf(mk, fabsf(kg[t + i * 32]));
        }
#pragma unroll
        for (int s = 16; s; s >>= 1) {
            mq = fmaxf(mq, __shfl_xor_sync(0xffffffffu, mq, s));
            mk = fmaxf(mk, __shfl_xor_sync(0xffffffffu, mk, s));
        }
        if (t == 0) m2[0] = 16.32253f * mq * mk * 1.002f + 0.01f;
    }
    const int total = N0_ + N1_ + N2_;
    int i = blockIdx.x * blockDim.x + threadIdx.x;
    int stride = gridDim.x * blockDim.x;
    for (; i < total; i += stride) {
        const float4* src;
        float4* dst;
        int k;
        if (i < N0_)            { src = (const float4*)x;  dst = (float4*)xr;  k = i; }
        else if (i < N0_ + N1_) { src = (const float4*)wi; dst = (float4*)wir; k = i - N0_; }
        else                    { src = (const float4*)wo; dst = (float4*)wor; k = i - N0_ - N1_; }
        float4 v = src[k];
        v.x = tf32f(v.x); v.y = tf32f(v.y); v.z = tf32f(v.z); v.w = tf32f(v.w);
        dst[k] = v;
    }
}

// ---------------------------------------------------------------------------
// TF32 GEMM (identical to R4 known-good)
// ---------------------------------------------------------------------------
#define GLD 20
#define GST (128 * GLD)
template<bool ROUND>
__global__ __launch_bounds__(128, 2) void gemm_tf32_v2(
    const float* __restrict__ A, const float* __restrict__ W,
    float* __restrict__ C, int M, int N, int K)
{
    extern __shared__ float smem[];
    float* sA = smem;
    float* sB = smem + 3 * GST;
    const int t = threadIdx.x, warp = t >> 5, lane = t & 31;
    const int g = lane >> 2, tq = lane & 3, wy = warp >> 1, wx = warp & 1;
    const int m0 = blockIdx.y * 128, n0 = blockIdx.x * 128;
    const int lrow = t >> 2, lkq = t & 3;
    const float* Ab = A + (size_t)m0 * K;
    const float* Wb = W + (size_t)n0 * K;
    float acc[4][8][4];
#pragma unroll
    for (int i = 0; i < 4; i++)
#pragma unroll
        for (int j = 0; j < 8; j++)
#pragma unroll
            for (int r = 0; r < 4; r++) acc[i][j][r] = 0.f;
    auto issue = [&](int kc, int st) {
        int k0 = kc * 16;
#pragma unroll
        for (int u = 0; u < 4; u++) {
            int row = lrow + u * 32;
            cp_async16(&sA[st * GST + row * GLD + lkq * 4], Ab + (size_t)row * K + k0 + lkq * 4);
        }
#pragma unroll
        for (int u = 0; u < 4; u++) {
            int row = lrow + u * 32;
            cp_async16(&sB[st * GST + row * GLD + lkq * 4], Wb + (size_t)row * K + k0 + lkq * 4);
        }
        cp_commit();
    };
    const int nk = K / 16;
    issue(0, 0); issue(1, 1);
    for (int kc = 0; kc < nk; kc++) {
        if (kc + 1 < nk) cp_wait1(); else cp_wait0();
        __syncthreads();
        if (kc + 2 < nk) issue(kc + 2, (kc + 2) % 3);
        const float* cA = &sA[(kc % 3) * GST];
        const float* cB = &sB[(kc % 3) * GST];
#pragma unroll
        for (int ks = 0; ks < 2; ks++) {
            unsigned af[4][4];
#pragma unroll
            for (int mt = 0; mt < 4; mt++) {
                const float* base = &cA[(wy * 64 + mt * 16 + g) * GLD + ks * 8 + tq];
                af[mt][0] = __float_as_uint(base[0]);
                af[mt][1] = __float_as_uint(base[8 * GLD]);
                af[mt][2] = __float_as_uint(base[4]);
                af[mt][3] = __float_as_uint(base[8 * GLD + 4]);
            }
            unsigned bf[8][2];
#pragma unroll
            for (int nt = 0; nt < 8; nt++) {
                const float* base = &cB[(wx * 64 + nt * 8 + g) * GLD + ks * 8 + tq];
                bf[nt][0] = __float_as_uint(base[0]);
                bf[nt][1] = __float_as_uint(base[4]);
            }
#pragma unroll
            for (int mt = 0; mt < 4; mt++)
#pragma unroll
                for (int nt = 0; nt < 8; nt++)
                    mma_tf32(acc[mt][nt][0], acc[mt][nt][1], acc[mt][nt][2], acc[mt][nt][3],
                             af[mt][0], af[mt][1], af[mt][2], af[mt][3], bf[nt][0], bf[nt][1]);
        }
    }
#pragma unroll
    for (int mt = 0; mt < 4; mt++) {
        int r0 = m0 + wy * 64 + mt * 16 + g;
#pragma unroll
        for (int nt = 0; nt < 8; nt++) {
            int col = n0 + wx * 64 + nt * 8 + tq * 2;
            float c0 = acc[mt][nt][0], c1 = acc[mt][nt][1];
            float c2 = acc[mt][nt][2], c3 = acc[mt][nt][3];
            if (ROUND) { c0 = tf32f(c0); c1 = tf32f(c1); c2 = tf32f(c2); c3 = tf32f(c3); }
            *reinterpret_cast<float2*>(C + (size_t)r0 * N + col)       = make_float2(c0, c1);
            *reinterpret_cast<float2*>(C + (size_t)(r0 + 8) * N + col) = make_float2(c2, c3);
        }
    }
}

// ---------------------------------------------------------------------------
// Fused: RMSNorm q/k -> interleaved buffers (blocks 0..32767)
//        + V pair repack (blocks 32768..65535)
// ---------------------------------------------------------------------------
__global__ void rms_vpack(const float* __restrict__ qkv,
                          const float* __restrict__ qg, const float* __restrict__ kg,
                          float* __restrict__ qf, float* __restrict__ kf,
                          float2* __restrict__ vf)
{
    if (blockIdx.x < 32768) {
        int warp = (blockIdx.x * blockDim.x + threadIdx.x) >> 5;
        int lane = threadIdx.x & 31;
        const int half = B_ * S_ * H_;
        int part = warp / half;
        int rem  = warp % half;
        int bs   = rem / H_;
        int h    = rem % H_;
        int b    = bs >> 11, s = bs & 2047;
        const float* p = qkv + (size_t)bs * E_ + part * D_ + h * HD_;
        float4 v = *reinterpret_cast<const float4*>(p + lane * 4);
        float ss = v.x*v.x + v.y*v.y + v.z*v.z + v.w*v.w;
#pragma unroll
        for (int o = 16; o; o >>= 1) ss += __shfl_xor_sync(0xffffffffu, ss, o);
        float sc = rsqrtf(ss * (1.0f / 128.0f) + EPS_);
        const float* gam = part ? kg : qg;
        float4 gv = *reinterpret_cast<const float4*>(gam + lane * 4);
        float o0 = tf32f(v.x * sc * gv.x);
        float o1 = tf32f(v.y * sc * gv.y);
        float o2 = tf32f(v.z * sc * gv.z);
        float o3 = tf32f(v.w * sc * gv.w);
        float* dst = (part ? kf : qf) + ((size_t)((b * 16 + h) * S_ + s)) * HD_
                   + (lane >> 1) * 8 + (lane & 1);
        dst[0] = o0; dst[2] = o1; dst[4] = o2; dst[6] = o3;
    } else {
        int idx = (blockIdx.x - 32768) * blockDim.x + threadIdx.x;   // 64*1024*128
        int d  = idx & 127;
        int pr = (idx >> 7) & 1023;
        int bh = idx >> 17;
        int b = bh >> 4, h = bh & 15;
        int s_lo = (pr >> 2) * 8 + (pr & 3);
        const float* base = qkv + (size_t)(b * S_ + s_lo) * E_ + 2 * D_ + h * HD_ + d;
        vf[idx] = make_float2(base[0], base[(size_t)4 * E_]);
    }
}

// ---------------------------------------------------------------------------
// Causal flash attention v5 (identical math to R9): tf32 MMA, fixed-max
// softmax, pair-interleaved LDS.64 frags, 2-stage cp.async ring, occ 3.
// ---------------------------------------------------------------------------
#define KSTRIDE 136
#define VSTRIDE 264
#define KSTB (32 * KSTRIDE * 4)
#define VSTB (16 * VSTRIDE * 4)
#define STAGEB (KSTB + VSTB)

__global__ __launch_bounds__(128, 3) void attn_v5(
    const float* __restrict__ qf_g, const float* __restrict__ kf_g,
    const float2* __restrict__ vf_g, const float* __restrict__ m2p,
    float* __restrict__ out)
{
    extern __shared__ __align__(16) char smc[];

    const int t    = threadIdx.x;
    const int w    = t >> 5;
    const int lane = t & 31;
    const int g    = lane >> 2;
    const int tq   = lane & 3;

    const int bh   = blockIdx.x >> 5;
    const int qblk = 31 - (blockIdx.x & 31);
    const int b    = bh >> 4;
    const int h    = bh & 15;

    const int q0  = qblk * 64;
    const int qg0 = q0 + w * 16 + g;
    const int qg1 = qg0 + 8;
    const float M2 = m2p[0];

    const float*  qb = qf_g + (size_t)bh * S_ * HD_;
    const char*   kb = (const char*)(kf_g + (size_t)bh * S_ * HD_);
    const char*   vb = (const char*)(vf_g + (size_t)bh * 1024 * HD_);

    unsigned qf[16][4];
#pragma unroll
    for (int ks = 0; ks < 16; ks++) {
        float2 lo = *reinterpret_cast<const float2*>(qb + (size_t)qg0 * HD_ + ks * 8 + tq * 2);
        float2 hi = *reinterpret_cast<const float2*>(qb + (size_t)qg1 * HD_ + ks * 8 + tq * 2);
        qf[ks][0] = __float_as_uint(lo.x);
        qf[ks][2] = __float_as_uint(lo.y);
        qf[ks][1] = __float_as_uint(hi.x);
        qf[ks][3] = __float_as_uint(hi.y);
    }

    float acc[16][4];
#pragma unroll
    for (int i = 0; i < 16; i++)
#pragma unroll
        for (int r = 0; r < 4; r++) acc[i][r] = 0.f;
    float l0 = 0.f, l1 = 0.f;
    const float sc2 = 0.08838834764831845f * 1.4426950408889634f;

    auto issue = [&](int j, int st) {
        char* kdst = smc + st * STAGEB;
        char* vdst = kdst + KSTB;
        const char* ksrc = kb + (size_t)j * 32 * 512;
        const char* vsrc = vb + (size_t)(j * 16) * 1024;
#pragma unroll
        for (int u = 0; u < 8; u++) {
            int c = u * 128 + t;
            int r = c >> 5, col = c & 31;
            cp_async16(kdst + r * (KSTRIDE * 4) + col * 16, ksrc + r * 512 + col * 16);
        }
#pragma unroll
        for (int u = 0; u < 8; u++) {
            int c = u * 128 + t;
            int r = c >> 6, col = c & 63;
            cp_async16(vdst + r * (VSTRIDE * 4) + col * 16, vsrc + r * 1024 + col * 16);
        }
        cp_commit();
    };

    const int nblk = 2 * qblk + 2;
    issue(0, 0);

    const int src0 = (lane & ~3) | (tq >> 1);
    const int src1 = src0 + 2;
    const bool odd = (tq & 1);

    for (int j = 0; j < nblk; j++) {
        cp_wait0();
        __syncthreads();
        if (j + 1 < nblk) issue(j + 1, (j + 1) & 1);

        const float* cK = (const float*)(smc + (j & 1) * STAGEB);
        const float* cV = (const float*)(smc + (j & 1) * STAGEB + KSTB);
        const int k0 = j * 32;

        float sa[4][4];
#pragma unroll
        for (int nt = 0; nt < 4; nt++)
#pragma unroll
            for (int r = 0; r < 4; r++) sa[nt][r] = 0.f;
#pragma unroll
        for (int ks = 0; ks < 16; ks++) {
#pragma unroll
            for (int nt = 0; nt < 4; nt++) {
                float2 bp = *reinterpret_cast<const float2*>(
                    &cK[(nt * 8 + g) * KSTRIDE + ks * 8 + tq * 2]);
                mma_tf32(sa[nt][0], sa[nt][1], sa[nt][2], sa[nt][3],
                         qf[ks][0], qf[ks][1], qf[ks][2], qf[ks][3],
                         __float_as_uint(bp.x), __float_as_uint(bp.y));
            }
        }

        if (k0 + 31 > q0 + w * 16) {
#pragma unroll
            for (int nt = 0; nt < 4; nt++) {
                int kva = k0 + nt * 8 + tq * 2;
                float p0 = ex2f(fmaf(sa[nt][0], sc2, -M2));
                float p1 = ex2f(fmaf(sa[nt][1], sc2, -M2));
                float p2 = ex2f(fmaf(sa[nt][2], sc2, -M2));
                float p3 = ex2f(fmaf(sa[nt][3], sc2, -M2));
                p0 = (kva     <= qg0) ? p0 : 0.f;
                p1 = (kva + 1 <= qg0) ? p1 : 0.f;
                p2 = (kva     <= qg1) ? p2 : 0.f;
                p3 = (kva + 1 <= qg1) ? p3 : 0.f;
                l0 += p0 + p1; l1 += p2 + p3;
                sa[nt][0] = tf32f(p0); sa[nt][1] = tf32f(p1);
                sa[nt][2] = tf32f(p2); sa[nt][3] = tf32f(p3);
            }
        } else {
#pragma unroll
            for (int nt = 0; nt < 4; nt++) {
                float p0 = ex2f(fmaf(sa[nt][0], sc2, -M2));
                float p1 = ex2f(fmaf(sa[nt][1], sc2, -M2));
                float p2 = ex2f(fmaf(sa[nt][2], sc2, -M2));
                float p3 = ex2f(fmaf(sa[nt][3], sc2, -M2));
                l0 += p0 + p1; l1 += p2 + p3;
                sa[nt][0] = tf32f(p0); sa[nt][1] = tf32f(p1);
                sa[nt][2] = tf32f(p2); sa[nt][3] = tf32f(p3);
            }
        }

#pragma unroll
        for (int ks = 0; ks < 4; ks++) {
            float e0 = __shfl_sync(0xffffffffu, sa[ks][0], src0);
            float e1 = __shfl_sync(0xffffffffu, sa[ks][1], src0);
            float f0 = __shfl_sync(0xffffffffu, sa[ks][0], src1);
            float f1 = __shfl_sync(0xffffffffu, sa[ks][1], src1);
            float e2 = __shfl_sync(0xffffffffu, sa[ks][2], src0);
            float e3 = __shfl_sync(0xffffffffu, sa[ks][3], src0);
            float f2 = __shfl_sync(0xffffffffu, sa[ks][2], src1);
            float f3 = __shfl_sync(0xffffffffu, sa[ks][3], src1);
            unsigned a0 = __float_as_uint(odd ? e1 : e0);
            unsigned a2 = __float_as_uint(odd ? f1 : f0);
            unsigned a1 = __float_as_uint(odd ? e3 : e2);
            unsigned a3 = __float_as_uint(odd ? f3 : f2);
            const float* vr = &cV[(ks * 4 + tq) * VSTRIDE];
#pragma unroll
            for (int nt = 0; nt < 16; nt++) {
                float2 bp = *reinterpret_cast<const float2*>(vr + (nt * 8 + g) * 2);
                mma_tf32(acc[nt][0], acc[nt][1], acc[nt][2], acc[nt][3],
                         a0, a1, a2, a3,
                         __float_as_uint(bp.x), __float_as_uint(bp.y));
            }
        }
    }

    l0 += __shfl_xor_sync(0xffffffffu, l0, 1);
    l0 += __shfl_xor_sync(0xffffffffu, l0, 2);
    l1 += __shfl_xor_sync(0xffffffffu, l1, 1);
    l1 += __shfl_xor_sync(0xffffffffu, l1, 2);

    float inv0 = 1.0f / l0, inv1 = 1.0f / l1;
    float* o0 = out + (size_t)(b * S_ + qg0) * D_ + h * HD_;
    float* o1 = out + (size_t)(b * S_ + qg1) * D_ + h * HD_;
#pragma unroll
    for (int nt = 0; nt < 16; nt++) {
        int d = nt * 8 + tq * 2;
        *reinterpret_cast<float2*>(o0 + d) =
            make_float2(tf32f(acc[nt][0] * inv0), tf32f(acc[nt][1] * inv0));
        *reinterpret_cast<float2*>(o1 + d) =
            make_float2(tf32f(acc[nt][2] * inv1), tf32f(acc[nt][3] * inv1));
    }
}

// ---------------------------------------------------------------------------
extern "C" void kernel_launch(void* const* d_in, const int* in_sizes, int n_in,
                              void* d_out, int out_size)
{
    const float* x     = (const float*)d_in[0];
    const float* w_in  = (const float*)d_in[1];
    const float* w_out = (const float*)d_in[2];
    const float* qg    = (const float*)d_in[3];
    const float* kg    = (const float*)d_in[4];
    float* out = (float*)d_out;

    float *qkv, *att, *xr, *wir, *wor, *m2, *qf, *kf;
    float2* vf;
    cudaGetSymbolAddress((void**)&qkv, g_qkv);
    cudaGetSymbolAddress((void**)&att, g_att);
    cudaGetSymbolAddress((void**)&xr,  g_xr);
    cudaGetSymbolAddress((void**)&wir, g_wir);
    cudaGetSymbolAddress((void**)&wor, g_wor);
    cudaGetSymbolAddress((void**)&m2,  g_m2);
    cudaGetSymbolAddress((void**)&qf,  g_qf);
    cudaGetSymbolAddress((void**)&kf,  g_kf);
    cudaGetSymbolAddress((void**)&vf,  g_vf);

    const int gsm = 6 * GST * 4;
    cudaFuncSetAttribute(gemm_tf32_v2<true>,  cudaFuncAttributeMaxDynamicSharedMemorySize, gsm);
    cudaFuncSetAttribute(gemm_tf32_v2<false>, cudaFuncAttributeMaxDynamicSharedMemorySize, gsm);
    const int asm_ = 2 * STAGEB;
    cudaFuncSetAttribute(attn_v5, cudaFuncAttributeMaxDynamicSharedMemorySize, asm_);

    // 1) fused rounding prepass + gmax
    prep_all<<<2048, 256>>>(x, w_in, w_out, xr, wir, wor, qg, kg, m2);

    // 2) QKV projection (tf32, rounded epilogue)
    gemm_tf32_v2<true><<<dim3(E_ / 128, BS_ / 128), 128, gsm>>>(xr, wir, qkv, BS_, E_, D_);

    // 3) fused RMSNorm q/k pack + V pair pack
    rms_vpack<<<65536, 256>>>(qkv, qg, kg, qf, kf, vf);

    // 4) tf32 attention (fixed-max softmax)  <-- 4th launch: profiled by ncu
    attn_v5<<<64 * 32, 128, asm_>>>(qf, kf, vf, m2, att);

    // 5) output projection (tf32)
    gemm_tf32_v2<false><<<dim3(D_ / 128, BS_ / 128), 128, gsm>>>(att, wor, out, BS_, D_, D_);
}

// round 12
// speedup vs baseline: 1.8890x; 1.8828x over previous
#include <cuda_runtime.h>
#include <cuda_fp16.h>
#include <math.h>
#include <stdint.h>

#define B_ 4
#define S_ 2048
#define D_ 2048
#define H_ 16
#define HD_ 128
#define E_ 6144
#define BS_ 8192
#define EPS_ 1.1920929e-07f

__device__ float  g_qkv[(size_t)BS_ * E_];          // fp32 qkv
__device__ __half g_xh [(size_t)BS_ * D_];
__device__ __half g_wih[(size_t)E_  * D_];
__device__ __half g_woh[(size_t)D_  * D_];
__device__ __half g_ath[(size_t)BS_ * D_];          // attention out (fp16)
__device__ uint32_t g_qh[(size_t)64 * S_ * 64];     // [bh][s][64 u32 = 128 fp16]
__device__ uint32_t g_kh[(size_t)64 * S_ * 64];
__device__ uint32_t g_vh[(size_t)64 * 1024 * 128];  // [bh][pair-row][d]: (V[2p],V[2p+1])
__device__ float g_m2[1];

__device__ __forceinline__ float ex2f(float x) {
    float r; asm("ex2.approx.f32 %0, %1;" : "=f"(r) : "f"(x)); return r;
}
// pack two f32 -> f16x2 (first arg = HIGH half, second = LOW half)
__device__ __forceinline__ uint32_t pkh(float hi, float lo) {
    uint32_t r; asm("cvt.rn.f16x2.f32 %0, %1, %2;" : "=r"(r) : "f"(hi), "f"(lo)); return r;
}
__device__ __forceinline__ void mma_f16(float& c0, float& c1, float& c2, float& c3,
                                        unsigned a0, unsigned a1, unsigned a2, unsigned a3,
                                        unsigned b0, unsigned b1) {
    asm volatile("mma.sync.aligned.m16n8k16.row.col.f32.f16.f16.f32 "
        "{%0,%1,%2,%3}, {%4,%5,%6,%7}, {%8,%9}, {%0,%1,%2,%3};\n"
        : "+f"(c0), "+f"(c1), "+f"(c2), "+f"(c3)
        : "r"(a0), "r"(a1), "r"(a2), "r"(a3), "r"(b0), "r"(b1));
}
__device__ __forceinline__ void cp_async16(void* sdst, const void* gsrc) {
    unsigned s = (unsigned)__cvta_generic_to_shared(sdst);
    asm volatile("cp.async.cg.shared.global [%0], [%1], 16;\n" :: "r"(s), "l"(gsrc));
}
__device__ __forceinline__ void cp_commit() { asm volatile("cp.async.commit_group;\n"); }
__device__ __forceinline__ void cp_wait0() { asm volatile("cp.async.wait_group 0;\n"); }
__device__ __forceinline__ void cp_wait1() { asm volatile("cp.async.wait_group 1;\n"); }

// ---------------------------------------------------------------------------
__global__ void tofp16(const float* __restrict__ src, __half* __restrict__ dst, int n4)
{
    int i = blockIdx.x * blockDim.x + threadIdx.x;
    int st = gridDim.x * blockDim.x;
    for (; i < n4; i += st) {
        float4 v = reinterpret_cast<const float4*>(src)[i];
        uint2 o;
        o.x = pkh(v.y, v.x);
        o.y = pkh(v.w, v.z);
        reinterpret_cast<uint2*>(dst)[i] = o;
    }
}

__global__ void gmax_kernel(const float* __restrict__ qg, const float* __restrict__ kg,
                            float* __restrict__ o)
{
    int t = threadIdx.x;
    float mq = 0.f, mk = 0.f;
#pragma unroll
    for (int i = 0; i < 4; i++) {
        mq = fmaxf(mq, fabsf(qg[t + i * 32]));
        mk = fmaxf(mk, fabsf(kg[t + i * 32]));
    }
#pragma unroll
    for (int s = 16; s; s >>= 1) {
        mq = fmaxf(mq, __shfl_xor_sync(0xffffffffu, mq, s));
        mk = fmaxf(mk, __shfl_xor_sync(0xffffffffu, mk, s));
    }
    if (t == 0) o[0] = 16.32253f * mq * mk * 1.002f + 0.01f;
}

// ---------------------------------------------------------------------------
// FP16 GEMM: C[m][n] = sum_k A[m][k]*W[n][k] (fp32 accum/out). CTA 128x128,
// BK=32, 128 thr, 4 warps 2x2, warp tile 64x64, m16n8k16, 3-stage cp.async.
// smem stride 40 halves (20 words, ==4 mod 32: conflict-free frags).
// ---------------------------------------------------------------------------
#define HLD 40
#define HST (128 * HLD)
#define HSTAGE (2 * HST)

__global__ __launch_bounds__(128, 2) void gemm_f16(
    const __half* __restrict__ A, const __half* __restrict__ W,
    float* __restrict__ C, int M, int N, int K)
{
    extern __shared__ __half smh[];
    const int t = threadIdx.x, warp = t >> 5, lane = t & 31;
    const int g = lane >> 2, tq = lane & 3, wy = warp >> 1, wx = warp & 1;
    const int m0 = blockIdx.y * 128, n0 = blockIdx.x * 128;
    const int lrow = t >> 2, lc = t & 3;
    const __half* Ab = A + (size_t)m0 * K;
    const __half* Wb = W + (size_t)n0 * K;

    float acc[4][8][4];
#pragma unroll
    for (int i = 0; i < 4; i++)
#pragma unroll
        for (int j = 0; j < 8; j++)
#pragma unroll
            for (int r = 0; r < 4; r++) acc[i][j][r] = 0.f;

    auto issue = [&](int kc, int st) {
        int k0 = kc * 32;
        __half* sa = smh + st * HSTAGE;
        __half* sb = sa + HST;
#pragma unroll
        for (int u = 0; u < 4; u++) {
            int row = lrow + u * 32;
            cp_async16(sa + row * HLD + lc * 8, Ab + (size_t)row * K + k0 + lc * 8);
        }
#pragma unroll
        for (int u = 0; u < 4; u++) {
            int row = lrow + u * 32;
            cp_async16(sb + row * HLD + lc * 8, Wb + (size_t)row * K + k0 + lc * 8);
        }
        cp_commit();
    };

    const int nk = K / 32;
    issue(0, 0); issue(1, 1);
    for (int kc = 0; kc < nk; kc++) {
        if (kc + 1 < nk) cp_wait1(); else cp_wait0();
        __syncthreads();
        if (kc + 2 < nk) issue(kc + 2, (kc + 2) % 3);
        const __half* sa = smh + (kc % 3) * HSTAGE;
        const __half* sb = sa + HST;
#pragma unroll
        for (int ks = 0; ks < 2; ks++) {
            unsigned af[4][4];
#pragma unroll
            for (int mt = 0; mt < 4; mt++) {
                const __half* base = sa + (wy * 64 + mt * 16 + g) * HLD + ks * 16 + tq * 2;
                af[mt][0] = *reinterpret_cast<const unsigned*>(base);
                af[mt][1] = *reinterpret_cast<const unsigned*>(base + 8 * HLD);
                af[mt][2] = *reinterpret_cast<const unsigned*>(base + 8);
                af[mt][3] = *reinterpret_cast<const unsigned*>(base + 8 * HLD + 8);
            }
            unsigned bf[8][2];
#pragma unroll
            for (int nt = 0; nt < 8; nt++) {
                const __half* base = sb + (wx * 64 + nt * 8 + g) * HLD + ks * 16 + tq * 2;
                bf[nt][0] = *reinterpret_cast<const unsigned*>(base);
                bf[nt][1] = *reinterpret_cast<const unsigned*>(base + 8);
            }
#pragma unroll
            for (int mt = 0; mt < 4; mt++)
#pragma unroll
                for (int nt = 0; nt < 8; nt++)
                    mma_f16(acc[mt][nt][0], acc[mt][nt][1], acc[mt][nt][2], acc[mt][nt][3],
                            af[mt][0], af[mt][1], af[mt][2], af[mt][3], bf[nt][0], bf[nt][1]);
        }
    }
#pragma unroll
    for (int mt = 0; mt < 4; mt++) {
        int r0 = m0 + wy * 64 + mt * 16 + g;
#pragma unroll
        for (int nt = 0; nt < 8; nt++) {
            int col = n0 + wx * 64 + nt * 8 + tq * 2;
            *reinterpret_cast<float2*>(C + (size_t)r0 * N + col) =
                make_float2(acc[mt][nt][0], acc[mt][nt][1]);
            *reinterpret_cast<float2*>(C + (size_t)(r0 + 8) * N + col) =
                make_float2(acc[mt][nt][2], acc[mt][nt][3]);
        }
    }
}

// ---------------------------------------------------------------------------
// Fused: RMSNorm q/k -> fp16 head-major (blocks < 32768) + V pair-pack (rest)
// ---------------------------------------------------------------------------
__global__ void rms_vpack(const float* __restrict__ qkv,
                          const float* __restrict__ qg, const float* __restrict__ kg,
                          uint32_t* __restrict__ qh, uint32_t* __restrict__ kh,
                          uint32_t* __restrict__ vh)
{
    if (blockIdx.x < 32768) {
        int warp = (blockIdx.x * blockDim.x + threadIdx.x) >> 5;
        int lane = threadIdx.x & 31;
        const int half = B_ * S_ * H_;
        int part = warp / half;
        int rem  = warp % half;
        int bs   = rem / H_;
        int h    = rem % H_;
        int b    = bs >> 11, s = bs & 2047;
        const float* p = qkv + (size_t)bs * E_ + part * D_ + h * HD_;
        float4 v = *reinterpret_cast<const float4*>(p + lane * 4);
        float ss = v.x*v.x + v.y*v.y + v.z*v.z + v.w*v.w;
#pragma unroll
        for (int o = 16; o; o >>= 1) ss += __shfl_xor_sync(0xffffffffu, ss, o);
        float sc = rsqrtf(ss * (1.0f / 128.0f) + EPS_);
        const float* gam = part ? kg : qg;
        float4 gv = *reinterpret_cast<const float4*>(gam + lane * 4);
        uint2 o2;
        o2.x = pkh(v.y * sc * gv.y, v.x * sc * gv.x);
        o2.y = pkh(v.w * sc * gv.w, v.z * sc * gv.z);
        uint32_t* dst = (part ? kh : qh) + ((size_t)((b * 16 + h) * S_ + s)) * 64 + lane * 2;
        *reinterpret_cast<uint2*>(dst) = o2;
    } else {
        int idx = (blockIdx.x - 32768) * blockDim.x + threadIdx.x;  // 64*1024*128
        int d  = idx & 127;
        int pr = (idx >> 7) & 1023;
        int bh = idx >> 17;
        int b = bh >> 4, h = bh & 15;
        const float* base = qkv + (size_t)(b * S_ + pr * 2) * E_ + 2 * D_ + h * HD_ + d;
        vh[idx] = pkh(base[E_], base[0]);  // lo = V[2pr], hi = V[2pr+1]
    }
}

// ---------------------------------------------------------------------------
// fp16 causal flash attention, fixed-max softmax with +2^13 P-scaling
// (cancelled exactly by normalization; keeps P out of fp16 denormal range).
// 128 thr = 4 warps, BQ=64, BKV=32, 3-stage cp.async, m16n8k16.
// ---------------------------------------------------------------------------
#define KLDU 68
#define VLDU 136
#define KSTB (32 * KLDU * 4)
#define VSTB (16 * VLDU * 4)
#define STAGEB (KSTB + VSTB)

__global__ __launch_bounds__(128, 3) void attn_h(
    const uint32_t* __restrict__ qh, const uint32_t* __restrict__ kh,
    const uint32_t* __restrict__ vh, const float* __restrict__ m2p,
    __half* __restrict__ out)
{
    extern __shared__ __align__(16) char smc[];

    const int t    = threadIdx.x;
    const int w    = t >> 5;
    const int lane = t & 31;
    const int g    = lane >> 2;
    const int tq   = lane & 3;

    const int bh   = blockIdx.x >> 5;
    const int qblk = 31 - (blockIdx.x & 31);
    const int b    = bh >> 4;
    const int h    = bh & 15;

    const int q0  = qblk * 64;
    const int qg0 = q0 + w * 16 + g;
    const int qg1 = qg0 + 8;
    const float MB = m2p[0] - 13.0f;   // P scaled by 2^13: avoids fp16 denormal flush

    const uint32_t* qb32 = qh + (size_t)bh * S_ * 64;
    const char*     kbp  = (const char*)(kh + (size_t)bh * S_ * 64);
    const char*     vbp  = (const char*)(vh + (size_t)bh * 1024 * 128);

    unsigned qf[8][4];
#pragma unroll
    for (int ks = 0; ks < 8; ks++) {
        qf[ks][0] = qb32[(size_t)qg0 * 64 + ks * 8 + tq];
        qf[ks][1] = qb32[(size_t)qg1 * 64 + ks * 8 + tq];
        qf[ks][2] = qb32[(size_t)qg0 * 64 + ks * 8 + tq + 4];
        qf[ks][3] = qb32[(size_t)qg1 * 64 + ks * 8 + tq + 4];
    }

    float acc[16][4];
#pragma unroll
    for (int i = 0; i < 16; i++)
#pragma unroll
        for (int r = 0; r < 4; r++) acc[i][r] = 0.f;
    float l0 = 0.f, l1 = 0.f;
    const float sc2 = 0.08838834764831845f * 1.4426950408889634f;

    auto issue = [&](int j, int st) {
        char* kdst = smc + st * STAGEB;
        char* vdst = kdst + KSTB;
        const char* ksrc = kbp + (size_t)j * 32 * 256;
        const char* vsrc = vbp + (size_t)j * 16 * 512;
#pragma unroll
        for (int u = 0; u < 4; u++) {
            int c = u * 128 + t;
            int r = c >> 4, col = c & 15;
            cp_async16(kdst + r * 272 + col * 16, ksrc + r * 256 + col * 16);
        }
#pragma unroll
        for (int u = 0; u < 4; u++) {
            int c = u * 128 + t;
            int r = c >> 5, col = c & 31;
            cp_async16(vdst + r * 544 + col * 16, vsrc + r * 512 + col * 16);
        }
        cp_commit();
    };

    const int nblk = 2 * qblk + 2;
    issue(0, 0);
    issue(1, 1);

    for (int j = 0; j < nblk; j++) {
        if (j + 1 < nblk) cp_wait1(); else cp_wait0();
        __syncthreads();
        if (j + 2 < nblk) issue(j + 2, (j + 2) % 3);

        const uint32_t* cK = (const uint32_t*)(smc + (j % 3) * STAGEB);
        const uint32_t* cV = (const uint32_t*)(smc + (j % 3) * STAGEB + KSTB);
        const int k0 = j * 32;

        // ---- S = Q K^T ----
        float sa[4][4];
#pragma unroll
        for (int nt = 0; nt < 4; nt++)
#pragma unroll
            for (int r = 0; r < 4; r++) sa[nt][r] = 0.f;
#pragma unroll
        for (int ks = 0; ks < 8; ks++) {
#pragma unroll
            for (int nt = 0; nt < 4; nt++) {
                unsigned b0 = cK[(nt * 8 + g) * KLDU + ks * 8 + tq];
                unsigned b1 = cK[(nt * 8 + g) * KLDU + ks * 8 + tq + 4];
                mma_f16(sa[nt][0], sa[nt][1], sa[nt][2], sa[nt][3],
                        qf[ks][0], qf[ks][1], qf[ks][2], qf[ks][3], b0, b1);
            }
        }

        // ---- fixed-max softmax (scaled by 2^13) ----
        if (k0 + 31 > q0 + w * 16) {
#pragma unroll
            for (int nt = 0; nt < 4; nt++) {
                int kva = k0 + nt * 8 + tq * 2;
                float p0 = ex2f(fmaf(sa[nt][0], sc2, -MB));
                float p1 = ex2f(fmaf(sa[nt][1], sc2, -MB));
                float p2 = ex2f(fmaf(sa[nt][2], sc2, -MB));
                float p3 = ex2f(fmaf(sa[nt][3], sc2, -MB));
                p0 = (kva     <= qg0) ? p0 : 0.f;
                p1 = (kva + 1 <= qg0) ? p1 : 0.f;
                p2 = (kva     <= qg1) ? p2 : 0.f;
                p3 = (kva + 1 <= qg1) ? p3 : 0.f;
                l0 += p0 + p1; l1 += p2 + p3;
                sa[nt][0] = p0; sa[nt][1] = p1; sa[nt][2] = p2; sa[nt][3] = p3;
            }
        } else {
#pragma unroll
            for (int nt = 0; nt < 4; nt++) {
                float p0 = ex2f(fmaf(sa[nt][0], sc2, -MB));
                float p1 = ex2f(fmaf(sa[nt][1], sc2, -MB));
                float p2 = ex2f(fmaf(sa[nt][2], sc2, -MB));
                float p3 = ex2f(fmaf(sa[nt][3], sc2, -MB));
                l0 += p0 + p1; l1 += p2 + p3;
                sa[nt][0] = p0; sa[nt][1] = p1; sa[nt][2] = p2; sa[nt][3] = p3;
            }
        }

        // ---- PV: C-frags -> fp16 A-frags directly (no shuffles) ----
#pragma unroll
        for (int i = 0; i < 2; i++) {
            unsigned a0 = pkh(sa[2*i][1],   sa[2*i][0]);
            unsigned a1 = pkh(sa[2*i][3],   sa[2*i][2]);
            unsigned a2 = pkh(sa[2*i+1][1], sa[2*i+1][0]);
            unsigned a3 = pkh(sa[2*i+1][3], sa[2*i+1][2]);
            const uint32_t* vr0 = &cV[(i * 8 + tq) * VLDU];
            const uint32_t* vr1 = &cV[(i * 8 + tq + 4) * VLDU];
#pragma unroll
            for (int nt = 0; nt < 16; nt++) {
                mma_f16(acc[nt][0], acc[nt][1], acc[nt][2], acc[nt][3],
                        a0, a1, a2, a3, vr0[nt * 8 + g], vr1[nt * 8 + g]);
            }
        }
    }

    l0 += __shfl_xor_sync(0xffffffffu, l0, 1);
    l0 += __shfl_xor_sync(0xffffffffu, l0, 2);
    l1 += __shfl_xor_sync(0xffffffffu, l1, 1);
    l1 += __shfl_xor_sync(0xffffffffu, l1, 2);

    float inv0 = 1.0f / l0, inv1 = 1.0f / l1;   // scale 2^13 cancels exactly
    uint32_t* o0 = (uint32_t*)(out + (size_t)(b * S_ + qg0) * D_ + h * HD_);
    uint32_t* o1 = (uint32_t*)(out + (size_t)(b * S_ + qg1) * D_ + h * HD_);
#pragma unroll
    for (int nt = 0; nt < 16; nt++) {
        o0[nt * 4 + tq] = pkh(acc[nt][1] * inv0, acc[nt][0] * inv0);
        o1[nt * 4 + tq] = pkh(acc[nt][3] * inv1, acc[nt][2] * inv1);
    }
}

// ---------------------------------------------------------------------------
extern "C" void kernel_launch(void* const* d_in, const int* in_sizes, int n_in,
                              void* d_out, int out_size)
{
    const float* x     = (const float*)d_in[0];
    const float* w_in  = (const float*)d_in[1];
    const float* w_out = (const float*)d_in[2];
    const float* qg    = (const float*)d_in[3];
    const float* kg    = (const float*)d_in[4];
    float* out = (float*)d_out;

    float *qkv, *m2;
    __half *xh, *wih, *woh, *ath;
    uint32_t *qh, *kh, *vh;
    cudaGetSymbolAddress((void**)&qkv, g_qkv);
    cudaGetSymbolAddress((void**)&m2,  g_m2);
    cudaGetSymbolAddress((void**)&xh,  g_xh);
    cudaGetSymbolAddress((void**)&wih, g_wih);
    cudaGetSymbolAddress((void**)&woh, g_woh);
    cudaGetSymbolAddress((void**)&ath, g_ath);
    cudaGetSymbolAddress((void**)&qh,  g_qh);
    cudaGetSymbolAddress((void**)&kh,  g_kh);
    cudaGetSymbolAddress((void**)&vh,  g_vh);

    const int gsm = 3 * HSTAGE * 2;   // 61440 B
    cudaFuncSetAttribute(gemm_f16, cudaFuncAttributeMaxDynamicSharedMemorySize, gsm);
    const int asm_ = 3 * STAGEB;      // 52224 B
    cudaFuncSetAttribute(attn_h, cudaFuncAttributeMaxDynamicSharedMemorySize, asm_);

    // 1-3) fp16 conversions + gmax
    tofp16<<<1184, 256>>>(x, xh, BS_ * D_ / 4);
    tofp16<<<1184, 256>>>(w_in, wih, E_ * D_ / 4);
    gmax_kernel<<<1, 32>>>(qg, kg, m2);

    // 4) QKV projection (fp16 MMA, fp32 out)  <-- 4th launch: profiled
    gemm_f16<<<dim3(E_ / 128, BS_ / 128), 128, gsm>>>(xh, wih, qkv, BS_, E_, D_);

    // 5) w_out conversion
    tofp16<<<1184, 256>>>(w_out, woh, D_ * D_ / 4);

    // 6) RMSNorm q/k -> fp16 + V pair pack
    rms_vpack<<<65536, 256>>>(qkv, qg, kg, qh, kh, vh);

    // 7) fp16 attention -> fp16 O
    attn_h<<<64 * 32, 128, asm_>>>(qh, kh, vh, m2, ath);

    // 8) output projection (fp16 MMA, fp32 out)
    gemm_f16<<<dim3(D_ / 128, BS_ / 128), 128, gsm>>>(ath, woh, out, BS_, D_, D_);
}

// round 13
// speedup vs baseline: 2.1637x; 1.1454x over previous
#include <cuda_runtime.h>
#include <cuda_fp16.h>
#include <math.h>
#include <stdint.h>

#define B_ 4
#define S_ 2048
#define D_ 2048
#define H_ 16
#define HD_ 128
#define E_ 6144
#define BS_ 8192
#define EPS_ 1.1920929e-07f

__device__ float  g_qkv[(size_t)BS_ * E_];
__device__ __half g_xh [(size_t)BS_ * D_];
__device__ __half g_wih[(size_t)E_  * D_];
__device__ __half g_woh[(size_t)D_  * D_];
__device__ __half g_ath[(size_t)BS_ * D_];
__device__ uint32_t g_qh[(size_t)64 * S_ * 64];
__device__ uint32_t g_kh[(size_t)64 * S_ * 64];
__device__ uint32_t g_vh[(size_t)64 * 1024 * 128];
__device__ float g_m2[1];

__device__ __forceinline__ float ex2f(float x) {
    float r; asm("ex2.approx.f32 %0, %1;" : "=f"(r) : "f"(x)); return r;
}
__device__ __forceinline__ uint32_t pkh(float hi, float lo) {
    uint32_t r; asm("cvt.rn.f16x2.f32 %0, %1, %2;" : "=r"(r) : "f"(hi), "f"(lo)); return r;
}
__device__ __forceinline__ void mma_f16(float& c0, float& c1, float& c2, float& c3,
                                        unsigned a0, unsigned a1, unsigned a2, unsigned a3,
                                        unsigned b0, unsigned b1) {
    asm volatile("mma.sync.aligned.m16n8k16.row.col.f32.f16.f16.f32 "
        "{%0,%1,%2,%3}, {%4,%5,%6,%7}, {%8,%9}, {%0,%1,%2,%3};\n"
        : "+f"(c0), "+f"(c1), "+f"(c2), "+f"(c3)
        : "r"(a0), "r"(a1), "r"(a2), "r"(a3), "r"(b0), "r"(b1));
}
__device__ __forceinline__ void ldsm4(unsigned& r0, unsigned& r1, unsigned& r2, unsigned& r3,
                                      uint32_t addr) {
    asm volatile("ldmatrix.sync.aligned.m8n8.x4.shared.b16 {%0,%1,%2,%3}, [%4];"
        : "=r"(r0), "=r"(r1), "=r"(r2), "=r"(r3) : "r"(addr));
}
__device__ __forceinline__ void cp_async16(void* sdst, const void* gsrc) {
    unsigned s = (unsigned)__cvta_generic_to_shared(sdst);
    asm volatile("cp.async.cg.shared.global [%0], [%1], 16;\n" :: "r"(s), "l"(gsrc));
}
__device__ __forceinline__ void cp_commit() { asm volatile("cp.async.commit_group;\n"); }
__device__ __forceinline__ void cp_wait0() { asm volatile("cp.async.wait_group 0;\n"); }
__device__ __forceinline__ void cp_wait1() { asm volatile("cp.async.wait_group 1;\n"); }
__device__ __forceinline__ void cp_wait2() { asm volatile("cp.async.wait_group 2;\n"); }

// ---------------------------------------------------------------------------
__global__ void tofp16(const float* __restrict__ src, __half* __restrict__ dst, int n4)
{
    int i = blockIdx.x * blockDim.x + threadIdx.x;
    int st = gridDim.x * blockDim.x;
    for (; i < n4; i += st) {
        float4 v = reinterpret_cast<const float4*>(src)[i];
        uint2 o;
        o.x = pkh(v.y, v.x);
        o.y = pkh(v.w, v.z);
        reinterpret_cast<uint2*>(dst)[i] = o;
    }
}

__global__ void gmax_kernel(const float* __restrict__ qg, const float* __restrict__ kg,
                            float* __restrict__ o)
{
    int t = threadIdx.x;
    float mq = 0.f, mk = 0.f;
#pragma unroll
    for (int i = 0; i < 4; i++) {
        mq = fmaxf(mq, fabsf(qg[t + i * 32]));
        mk = fmaxf(mk, fabsf(kg[t + i * 32]));
    }
#pragma unroll
    for (int s = 16; s; s >>= 1) {
        mq = fmaxf(mq, __shfl_xor_sync(0xffffffffu, mq, s));
        mk = fmaxf(mk, __shfl_xor_sync(0xffffffffu, mk, s));
    }
    if (t == 0) o[0] = 16.32253f * mq * mk * 1.002f + 0.01f;
}

// ---------------------------------------------------------------------------
// FP16 GEMM v3: ldmatrix fragment loads, 4-stage cp.async. CTA 128x128, BK=32,
// 128 thr, warp tile 64x64. smem stride 40 halves (conflict-free LDSM).
// ---------------------------------------------------------------------------
#define HLD 40
#define HST (128 * HLD)
#define HSTAGE (2 * HST)
#define NSTG 4

__global__ __launch_bounds__(128, 2) void gemm_f16(
    const __half* __restrict__ A, const __half* __restrict__ W,
    float* __restrict__ C, int M, int N, int K)
{
    extern __shared__ __half smh[];
    const int t = threadIdx.x, warp = t >> 5, lane = t & 31;
    const int g = lane >> 2, tq = lane & 3, wy = warp >> 1, wx = warp & 1;
    const int m0 = blockIdx.y * 128, n0 = blockIdx.x * 128;
    const int lrow = t >> 2, lc = t & 3;
    const __half* Ab = A + (size_t)m0 * K;
    const __half* Wb = W + (size_t)n0 * K;

    const uint32_t su = (uint32_t)__cvta_generic_to_shared(smh);
    // ldmatrix per-thread base offsets (halves), within a stage
    const int arow = wy * 64 + (lane & 15);
    const int acol = (lane >> 4) * 8;
    const uint32_t aoff = su + (uint32_t)(arow * HLD + acol) * 2;
    const int brow = wx * 64 + ((lane >> 4) & 1) * 8 + (lane & 7);
    const int bcol = ((lane >> 3) & 1) * 8;
    const uint32_t boff = su + (uint32_t)(HST + brow * HLD + bcol) * 2;

    float acc[4][8][4];
#pragma unroll
    for (int i = 0; i < 4; i++)
#pragma unroll
        for (int j = 0; j < 8; j++)
#pragma unroll
            for (int r = 0; r < 4; r++) acc[i][j][r] = 0.f;

    auto issue = [&](int kc, int st) {
        int k0 = kc * 32;
        __half* sa = smh + st * HSTAGE;
        __half* sb = sa + HST;
#pragma unroll
        for (int u = 0; u < 4; u++) {
            int row = lrow + u * 32;
            cp_async16(sa + row * HLD + lc * 8, Ab + (size_t)row * K + k0 + lc * 8);
        }
#pragma unroll
        for (int u = 0; u < 4; u++) {
            int row = lrow + u * 32;
            cp_async16(sb + row * HLD + lc * 8, Wb + (size_t)row * K + k0 + lc * 8);
        }
        cp_commit();
    };

    const int nk = K / 32;
    issue(0, 0); issue(1, 1); issue(2, 2);

    for (int kc = 0; kc < nk; kc++) {
        if (kc + 2 < nk) cp_wait2();
        else if (kc + 1 < nk) cp_wait1();
        else cp_wait0();
        __syncthreads();
        if (kc + 3 < nk) issue(kc + 3, (kc + 3) & (NSTG - 1));

        const uint32_t stg = (uint32_t)((kc & (NSTG - 1)) * HSTAGE * 2);
#pragma unroll
        for (int ks = 0; ks < 2; ks++) {
            unsigned af[4][4];
#pragma unroll
            for (int mt = 0; mt < 4; mt++)
                ldsm4(af[mt][0], af[mt][1], af[mt][2], af[mt][3],
                      aoff + stg + (uint32_t)(mt * 16 * HLD + ks * 16) * 2);
            unsigned bf[8][2];
#pragma unroll
            for (int tp = 0; tp < 4; tp++)
                ldsm4(bf[2*tp][0], bf[2*tp][1], bf[2*tp+1][0], bf[2*tp+1][1],
                      boff + stg + (uint32_t)(tp * 16 * HLD + ks * 16) * 2);
#pragma unroll
            for (int mt = 0; mt < 4; mt++)
#pragma unroll
                for (int nt = 0; nt < 8; nt++)
                    mma_f16(acc[mt][nt][0], acc[mt][nt][1], acc[mt][nt][2], acc[mt][nt][3],
                            af[mt][0], af[mt][1], af[mt][2], af[mt][3], bf[nt][0], bf[nt][1]);
        }
    }
#pragma unroll
    for (int mt = 0; mt < 4; mt++) {
        int r0 = m0 + wy * 64 + mt * 16 + g;
#pragma unroll
        for (int nt = 0; nt < 8; nt++) {
            int col = n0 + wx * 64 + nt * 8 + tq * 2;
            *reinterpret_cast<float2*>(C + (size_t)r0 * N + col) =
                make_float2(acc[mt][nt][0], acc[mt][nt][1]);
            *reinterpret_cast<float2*>(C + (size_t)(r0 + 8) * N + col) =
                make_float2(acc[mt][nt][2], acc[mt][nt][3]);
        }
    }
}

// ---------------------------------------------------------------------------
// Fused: RMSNorm q/k -> fp16 head-major (blocks < 32768) + V pair-pack (rest)
// ---------------------------------------------------------------------------
__global__ void rms_vpack(const float* __restrict__ qkv,
                          const float* __restrict__ qg, const float* __restrict__ kg,
                          uint32_t* __restrict__ qh, uint32_t* __restrict__ kh,
                          uint32_t* __restrict__ vh)
{
    if (blockIdx.x < 32768) {
        int warp = (blockIdx.x * blockDim.x + threadIdx.x) >> 5;
        int lane = threadIdx.x & 31;
        const int half = B_ * S_ * H_;
        int part = warp / half;
        int rem  = warp % half;
        int bs   = rem / H_;
        int h    = rem % H_;
        int b    = bs >> 11, s = bs & 2047;
        const float* p = qkv + (size_t)bs * E_ + part * D_ + h * HD_;
        float4 v = *reinterpret_cast<const float4*>(p + lane * 4);
        float ss = v.x*v.x + v.y*v.y + v.z*v.z + v.w*v.w;
#pragma unroll
        for (int o = 16; o; o >>= 1) ss += __shfl_xor_sync(0xffffffffu, ss, o);
        float sc = rsqrtf(ss * (1.0f / 128.0f) + EPS_);
        const float* gam = part ? kg : qg;
        float4 gv = *reinterpret_cast<const float4*>(gam + lane * 4);
        uint2 o2;
        o2.x = pkh(v.y * sc * gv.y, v.x * sc * gv.x);
        o2.y = pkh(v.w * sc * gv.w, v.z * sc * gv.z);
        uint32_t* dst = (part ? kh : qh) + ((size_t)((b * 16 + h) * S_ + s)) * 64 + lane * 2;
        *reinterpret_cast<uint2*>(dst) = o2;
    } else {
        int idx = (blockIdx.x - 32768) * blockDim.x + threadIdx.x;
        int d  = idx & 127;
        int pr = (idx >> 7) & 1023;
        int bh = idx >> 17;
        int b = bh >> 4, h = bh & 15;
        const float* base = qkv + (size_t)(b * S_ + pr * 2) * E_ + 2 * D_ + h * HD_ + d;
        vh[idx] = pkh(base[E_], base[0]);
    }
}

// ---------------------------------------------------------------------------
// fp16 causal flash attention (identical to R12 passing version)
// ---------------------------------------------------------------------------
#define KLDU 68
#define VLDU 136
#define KSTB (32 * KLDU * 4)
#define VSTB (16 * VLDU * 4)
#define STAGEB (KSTB + VSTB)

__global__ __launch_bounds__(128, 3) void attn_h(
    const uint32_t* __restrict__ qh, const uint32_t* __restrict__ kh,
    const uint32_t* __restrict__ vh, const float* __restrict__ m2p,
    __half* __restrict__ out)
{
    extern __shared__ __align__(16) char smc[];

    const int t    = threadIdx.x;
    const int w    = t >> 5;
    const int lane = t & 31;
    const int g    = lane >> 2;
    const int tq   = lane & 3;

    const int bh   = blockIdx.x >> 5;
    const int qblk = 31 - (blockIdx.x & 31);
    const int b    = bh >> 4;
    const int h    = bh & 15;

    const int q0  = qblk * 64;
    const int qg0 = q0 + w * 16 + g;
    const int qg1 = qg0 + 8;
    const float MB = m2p[0] - 13.0f;

    const uint32_t* qb32 = qh + (size_t)bh * S_ * 64;
    const char*     kbp  = (const char*)(kh + (size_t)bh * S_ * 64);
    const char*     vbp  = (const char*)(vh + (size_t)bh * 1024 * 128);

    unsigned qf[8][4];
#pragma unroll
    for (int ks = 0; ks < 8; ks++) {
        qf[ks][0] = qb32[(size_t)qg0 * 64 + ks * 8 + tq];
        qf[ks][1] = qb32[(size_t)qg1 * 64 + ks * 8 + tq];
        qf[ks][2] = qb32[(size_t)qg0 * 64 + ks * 8 + tq + 4];
        qf[ks][3] = qb32[(size_t)qg1 * 64 + ks * 8 + tq + 4];
    }

    float acc[16][4];
#pragma unroll
    for (int i = 0; i < 16; i++)
#pragma unroll
        for (int r = 0; r < 4; r++) acc[i][r] = 0.f;
    float l0 = 0.f, l1 = 0.f;
    const float sc2 = 0.08838834764831845f * 1.4426950408889634f;

    auto issue = [&](int j, int st) {
        char* kdst = smc + st * STAGEB;
        char* vdst = kdst + KSTB;
        const char* ksrc = kbp + (size_t)j * 32 * 256;
        const char* vsrc = vbp + (size_t)j * 16 * 512;
#pragma unroll
        for (int u = 0; u < 4; u++) {
            int c = u * 128 + t;
            int r = c >> 4, col = c & 15;
            cp_async16(kdst + r * 272 + col * 16, ksrc + r * 256 + col * 16);
        }
#pragma unroll
        for (int u = 0; u < 4; u++) {
            int c = u * 128 + t;
            int r = c >> 5, col = c & 31;
            cp_async16(vdst + r * 544 + col * 16, vsrc + r * 512 + col * 16);
        }
        cp_commit();
    };

    const int nblk = 2 * qblk + 2;
    issue(0, 0);
    issue(1, 1);

    for (int j = 0; j < nblk; j++) {
        if (j + 1 < nblk) cp_wait1(); else cp_wait0();
        __syncthreads();
        if (j + 2 < nblk) issue(j + 2, (j + 2) % 3);

        const uint32_t* cK = (const uint32_t*)(smc + (j % 3) * STAGEB);
        const uint32_t* cV = (const uint32_t*)(smc + (j % 3) * STAGEB + KSTB);
        const int k0 = j * 32;

        float sa[4][4];
#pragma unroll
        for (int nt = 0; nt < 4; nt++)
#pragma unroll
            for (int r = 0; r < 4; r++) sa[nt][r] = 0.f;
#pragma unroll
        for (int ks = 0; ks < 8; ks++) {
#pragma unroll
            for (int nt = 0; nt < 4; nt++) {
                unsigned b0 = cK[(nt * 8 + g) * KLDU + ks * 8 + tq];
                unsigned b1 = cK[(nt * 8 + g) * KLDU + ks * 8 + tq + 4];
                mma_f16(sa[nt][0], sa[nt][1], sa[nt][2], sa[nt][3],
                        qf[ks][0], qf[ks][1], qf[ks][2], qf[ks][3], b0, b1);
            }
        }

        if (k0 + 31 > q0 + w * 16) {
#pragma unroll
            for (int nt = 0; nt < 4; nt++) {
                int kva = k0 + nt * 8 + tq * 2;
                float p0 = ex2f(fmaf(sa[nt][0], sc2, -MB));
                float p1 = ex2f(fmaf(sa[nt][1], sc2, -MB));
                float p2 = ex2f(fmaf(sa[nt][2], sc2, -MB));
                float p3 = ex2f(fmaf(sa[nt][3], sc2, -MB));
                p0 = (kva     <= qg0) ? p0 : 0.f;
                p1 = (kva + 1 <= qg0) ? p1 : 0.f;
                p2 = (kva     <= qg1) ? p2 : 0.f;
                p3 = (kva + 1 <= qg1) ? p3 : 0.f;
                l0 += p0 + p1; l1 += p2 + p3;
                sa[nt][0] = p0; sa[nt][1] = p1; sa[nt][2] = p2; sa[nt][3] = p3;
            }
        } else {
#pragma unroll
            for (int nt = 0; nt < 4; nt++) {
                float p0 = ex2f(fmaf(sa[nt][0], sc2, -MB));
                float p1 = ex2f(fmaf(sa[nt][1], sc2, -MB));
                float p2 = ex2f(fmaf(sa[nt][2], sc2, -MB));
                float p3 = ex2f(fmaf(sa[nt][3], sc2, -MB));
                l0 += p0 + p1; l1 += p2 + p3;
                sa[nt][0] = p0; sa[nt][1] = p1; sa[nt][2] = p2; sa[nt][3] = p3;
            }
        }

#pragma unroll
        for (int i = 0; i < 2; i++) {
            unsigned a0 = pkh(sa[2*i][1],   sa[2*i][0]);
            unsigned a1 = pkh(sa[2*i][3],   sa[2*i][2]);
            unsigned a2 = pkh(sa[2*i+1][1], sa[2*i+1][0]);
            unsigned a3 = pkh(sa[2*i+1][3], sa[2*i+1][2]);
            const uint32_t* vr0 = &cV[(i * 8 + tq) * VLDU];
            const uint32_t* vr1 = &cV[(i * 8 + tq + 4) * VLDU];
#pragma unroll
            for (int nt = 0; nt < 16; nt++) {
                mma_f16(acc[nt][0], acc[nt][1], acc[nt][2], acc[nt][3],
                        a0, a1, a2, a3, vr0[nt * 8 + g], vr1[nt * 8 + g]);
            }
        }
    }

    l0 += __shfl_xor_sync(0xffffffffu, l0, 1);
    l0 += __shfl_xor_sync(0xffffffffu, l0, 2);
    l1 += __shfl_xor_sync(0xffffffffu, l1, 1);
    l1 += __shfl_xor_sync(0xffffffffu, l1, 2);

    float inv0 = 1.0f / l0, inv1 = 1.0f / l1;
    uint32_t* o0 = (uint32_t*)(out + (size_t)(b * S_ + qg0) * D_ + h * HD_);
    uint32_t* o1 = (uint32_t*)(out + (size_t)(b * S_ + qg1) * D_ + h * HD_);
#pragma unroll
    for (int nt = 0; nt < 16; nt++) {
        o0[nt * 4 + tq] = pkh(acc[nt][1] * inv0, acc[nt][0] * inv0);
        o1[nt * 4 + tq] = pkh(acc[nt][3] * inv1, acc[nt][2] * inv1);
    }
}

// ---------------------------------------------------------------------------
extern "C" void kernel_launch(void* const* d_in, const int* in_sizes, int n_in,
                              void* d_out, int out_size)
{
    const float* x     = (const float*)d_in[0];
    const float* w_in  = (const float*)d_in[1];
    const float* w_out = (const float*)d_in[2];
    const float* qg    = (const float*)d_in[3];
    const float* kg    = (const float*)d_in[4];
    float* out = (float*)d_out;

    float *qkv, *m2;
    __half *xh, *wih, *woh, *ath;
    uint32_t *qh, *kh, *vh;
    cudaGetSymbolAddress((void**)&qkv, g_qkv);
    cudaGetSymbolAddress((void**)&m2,  g_m2);
    cudaGetSymbolAddress((void**)&xh,  g_xh);
    cudaGetSymbolAddress((void**)&wih, g_wih);
    cudaGetSymbolAddress((void**)&woh, g_woh);
    cudaGetSymbolAddress((void**)&ath, g_ath);
    cudaGetSymbolAddress((void**)&qh,  g_qh);
    cudaGetSymbolAddress((void**)&kh,  g_kh);
    cudaGetSymbolAddress((void**)&vh,  g_vh);

    const int gsm = NSTG * HSTAGE * 2;   // 81920 B
    cudaFuncSetAttribute(gemm_f16, cudaFuncAttributeMaxDynamicSharedMemorySize, gsm);
    const int asm_ = 3 * STAGEB;         // 52224 B
    cudaFuncSetAttribute(attn_h, cudaFuncAttributeMaxDynamicSharedMemorySize, asm_);

    tofp16<<<1184, 256>>>(x, xh, BS_ * D_ / 4);
    tofp16<<<1184, 256>>>(w_in, wih, E_ * D_ / 4);
    gmax_kernel<<<1, 32>>>(qg, kg, m2);

    // 4th launch: profiled
    gemm_f16<<<dim3(E_ / 128, BS_ / 128), 128, gsm>>>(xh, wih, qkv, BS_, E_, D_);

    tofp16<<<1184, 256>>>(w_out, woh, D_ * D_ / 4);
    rms_vpack<<<65536, 256>>>(qkv, qg, kg, qh, kh, vh);
    attn_h<<<64 * 32, 128, asm_>>>(qh, kh, vh, m2, ath);
    gemm_f16<<<dim3(D_ / 128, BS_ / 128), 128, gsm>>>(ath, woh, out, BS_, D_, D_);
}

// round 14
// speedup vs baseline: 2.1762x; 1.0058x over previous
#include <cuda_runtime.h>
#include <cuda_fp16.h>
#include <math.h>
#include <stdint.h>

#define B_ 4
#define S_ 2048
#define D_ 2048
#define H_ 16
#define HD_ 128
#define E_ 6144
#define BS_ 8192
#define EPS_ 1.1920929e-07f

__device__ float  g_qkv[(size_t)BS_ * E_];
__device__ __half g_xh [(size_t)BS_ * D_];
__device__ __half g_wih[(size_t)E_  * D_];
__device__ __half g_woh[(size_t)D_  * D_];
__device__ __half g_ath[(size_t)BS_ * D_];
__device__ uint32_t g_qh[(size_t)64 * S_ * 64];
__device__ uint32_t g_kh[(size_t)64 * S_ * 64];
__device__ uint32_t g_vh[(size_t)64 * 1024 * 128];
__device__ float g_m2[1];

__device__ __forceinline__ float ex2f(float x) {
    float r; asm("ex2.approx.f32 %0, %1;" : "=f"(r) : "f"(x)); return r;
}
__device__ __forceinline__ uint32_t pkh(float hi, float lo) {
    uint32_t r; asm("cvt.rn.f16x2.f32 %0, %1, %2;" : "=r"(r) : "f"(hi), "f"(lo)); return r;
}
__device__ __forceinline__ void mma_f16(float& c0, float& c1, float& c2, float& c3,
                                        unsigned a0, unsigned a1, unsigned a2, unsigned a3,
                                        unsigned b0, unsigned b1) {
    asm volatile("mma.sync.aligned.m16n8k16.row.col.f32.f16.f16.f32 "
        "{%0,%1,%2,%3}, {%4,%5,%6,%7}, {%8,%9}, {%0,%1,%2,%3};\n"
        : "+f"(c0), "+f"(c1), "+f"(c2), "+f"(c3)
        : "r"(a0), "r"(a1), "r"(a2), "r"(a3), "r"(b0), "r"(b1));
}
__device__ __forceinline__ void ldsm4(unsigned& r0, unsigned& r1, unsigned& r2, unsigned& r3,
                                      uint32_t addr) {
    asm volatile("ldmatrix.sync.aligned.m8n8.x4.shared.b16 {%0,%1,%2,%3}, [%4];"
        : "=r"(r0), "=r"(r1), "=r"(r2), "=r"(r3) : "r"(addr));
}
__device__ __forceinline__ void cp_async16(void* sdst, const void* gsrc) {
    unsigned s = (unsigned)__cvta_generic_to_shared(sdst);
    asm volatile("cp.async.cg.shared.global [%0], [%1], 16;\n" :: "r"(s), "l"(gsrc));
}
__device__ __forceinline__ void cp_commit() { asm volatile("cp.async.commit_group;\n"); }
__device__ __forceinline__ void cp_wait0() { asm volatile("cp.async.wait_group 0;\n"); }
__device__ __forceinline__ void cp_wait1() { asm volatile("cp.async.wait_group 1;\n"); }

// ---------------------------------------------------------------------------
__global__ void tofp16(const float* __restrict__ src, __half* __restrict__ dst, int n4)
{
    int i = blockIdx.x * blockDim.x + threadIdx.x;
    int st = gridDim.x * blockDim.x;
    for (; i < n4; i += st) {
        float4 v = reinterpret_cast<const float4*>(src)[i];
        uint2 o;
        o.x = pkh(v.y, v.x);
        o.y = pkh(v.w, v.z);
        reinterpret_cast<uint2*>(dst)[i] = o;
    }
}

__global__ void gmax_kernel(const float* __restrict__ qg, const float* __restrict__ kg,
                            float* __restrict__ o)
{
    int t = threadIdx.x;
    float mq = 0.f, mk = 0.f;
#pragma unroll
    for (int i = 0; i < 4; i++) {
        mq = fmaxf(mq, fabsf(qg[t + i * 32]));
        mk = fmaxf(mk, fabsf(kg[t + i * 32]));
    }
#pragma unroll
    for (int s = 16; s; s >>= 1) {
        mq = fmaxf(mq, __shfl_xor_sync(0xffffffffu, mq, s));
        mk = fmaxf(mk, __shfl_xor_sync(0xffffffffu, mk, s));
    }
    if (t == 0) o[0] = 16.32253f * mq * mk * 1.002f + 0.01f;
}

// ---------------------------------------------------------------------------
// FP16 GEMM v4: BK=64, 3-stage cp.async, ldmatrix with double-buffered frags.
// CTA 128x128, 128 thr, warp tile 64x64. smem stride 72 halves (conflict-free).
// ---------------------------------------------------------------------------
#define HLD 72
#define HSTA (128 * HLD)              // halves per A (or B) tile
#define HSTAGE (2 * HSTA)             // halves per stage
#define STGB (HSTAGE * 2)             // bytes per stage (73728/2=36864)
#define NSTG 3

__global__ __launch_bounds__(128, 2) void gemm_f16(
    const __half* __restrict__ A, const __half* __restrict__ W,
    float* __restrict__ C, int M, int N, int K)
{
    extern __shared__ __half smh[];
    const int t = threadIdx.x, warp = t >> 5, lane = t & 31;
    const int g = lane >> 2, tq = lane & 3, wy = warp >> 1, wx = warp & 1;
    const int m0 = blockIdx.y * 128, n0 = blockIdx.x * 128;
    const __half* Ab = A + (size_t)m0 * K;
    const __half* Wb = W + (size_t)n0 * K;

    const uint32_t su = (uint32_t)__cvta_generic_to_shared(smh);
    const int arow = wy * 64 + (lane & 15);
    const int acol = (lane >> 4) * 8;
    const uint32_t aoff = su + (uint32_t)(arow * HLD + acol) * 2;
    const int brow = wx * 64 + ((lane >> 4) & 1) * 8 + (lane & 7);
    const int bcol = ((lane >> 3) & 1) * 8;
    const uint32_t boff = su + (uint32_t)(HSTA + brow * HLD + bcol) * 2;

    float acc[4][8][4];
#pragma unroll
    for (int i = 0; i < 4; i++)
#pragma unroll
        for (int j = 0; j < 8; j++)
#pragma unroll
            for (int r = 0; r < 4; r++) acc[i][j][r] = 0.f;

    auto issue = [&](int kc, int st) {
        int k0 = kc * 64;
        __half* sa = smh + st * HSTAGE;
        __half* sb = sa + HSTA;
#pragma unroll
        for (int u = 0; u < 8; u++) {              // A: 128 rows x 128B
            int c = u * 128 + t;
            int row = c >> 3, col = c & 7;
            cp_async16(sa + row * HLD + col * 8, Ab + (size_t)row * K + k0 + col * 8);
        }
#pragma unroll
        for (int u = 0; u < 8; u++) {              // B: 128 rows x 128B
            int c = u * 128 + t;
            int row = c >> 3, col = c & 7;
            cp_async16(sb + row * HLD + col * 8, Wb + (size_t)row * K + k0 + col * 8);
        }
        cp_commit();
    };

    unsigned af[2][4][4], bf[2][8][2];
    auto ldfr = [&](int ks, int buf, uint32_t stg) {
#pragma unroll
        for (int mt = 0; mt < 4; mt++)
            ldsm4(af[buf][mt][0], af[buf][mt][1], af[buf][mt][2], af[buf][mt][3],
                  aoff + stg + (uint32_t)(mt * 16 * HLD + ks * 16) * 2);
#pragma unroll
        for (int tp = 0; tp < 4; tp++)
            ldsm4(bf[buf][2*tp][0], bf[buf][2*tp][1], bf[buf][2*tp+1][0], bf[buf][2*tp+1][1],
                  boff + stg + (uint32_t)(tp * 16 * HLD + ks * 16) * 2);
    };

    const int nk = K / 64;
    issue(0, 0); issue(1, 1);

    for (int kc = 0; kc < nk; kc++) {
        if (kc + 1 < nk) cp_wait1(); else cp_wait0();
        __syncthreads();
        if (kc + 2 < nk) issue(kc + 2, (kc + 2) % NSTG);

        const uint32_t stg = (uint32_t)((kc % NSTG) * STGB);
        ldfr(0, 0, stg);
#pragma unroll
        for (int ks = 0; ks < 4; ks++) {
            if (ks < 3) ldfr(ks + 1, (ks + 1) & 1, stg);
            const int bu = ks & 1;
#pragma unroll
            for (int mt = 0; mt < 4; mt++)
#pragma unroll
                for (int nt = 0; nt < 8; nt++)
                    mma_f16(acc[mt][nt][0], acc[mt][nt][1], acc[mt][nt][2], acc[mt][nt][3],
                            af[bu][mt][0], af[bu][mt][1], af[bu][mt][2], af[bu][mt][3],
                            bf[bu][nt][0], bf[bu][nt][1]);
        }
    }
#pragma unroll
    for (int mt = 0; mt < 4; mt++) {
        int r0 = m0 + wy * 64 + mt * 16 + g;
#pragma unroll
        for (int nt = 0; nt < 8; nt++) {
            int col = n0 + wx * 64 + nt * 8 + tq * 2;
            *reinterpret_cast<float2*>(C + (size_t)r0 * N + col) =
                make_float2(acc[mt][nt][0], acc[mt][nt][1]);
            *reinterpret_cast<float2*>(C + (size_t)(r0 + 8) * N + col) =
                make_float2(acc[mt][nt][2], acc[mt][nt][3]);
        }
    }
}

// ---------------------------------------------------------------------------
// Fused: RMSNorm q/k -> fp16 head-major (blocks < 32768) + V pair-pack (rest)
// ---------------------------------------------------------------------------
__global__ void rms_vpack(const float* __restrict__ qkv,
                          const float* __restrict__ qg, const float* __restrict__ kg,
                          uint32_t* __restrict__ qh, uint32_t* __restrict__ kh,
                          uint32_t* __restrict__ vh)
{
    if (blockIdx.x < 32768) {
        int warp = (blockIdx.x * blockDim.x + threadIdx.x) >> 5;
        int lane = threadIdx.x & 31;
        const int half = B_ * S_ * H_;
        int part = warp / half;
        int rem  = warp % half;
        int bs   = rem / H_;
        int h    = rem % H_;
        int b    = bs >> 11, s = bs & 2047;
        const float* p = qkv + (size_t)bs * E_ + part * D_ + h * HD_;
        float4 v = *reinterpret_cast<const float4*>(p + lane * 4);
        float ss = v.x*v.x + v.y*v.y + v.z*v.z + v.w*v.w;
#pragma unroll
        for (int o = 16; o; o >>= 1) ss += __shfl_xor_sync(0xffffffffu, ss, o);
        float sc = rsqrtf(ss * (1.0f / 128.0f) + EPS_);
        const float* gam = part ? kg : qg;
        float4 gv = *reinterpret_cast<const float4*>(gam + lane * 4);
        uint2 o2;
        o2.x = pkh(v.y * sc * gv.y, v.x * sc * gv.x);
        o2.y = pkh(v.w * sc * gv.w, v.z * sc * gv.z);
        uint32_t* dst = (part ? kh : qh) + ((size_t)((b * 16 + h) * S_ + s)) * 64 + lane * 2;
        *reinterpret_cast<uint2*>(dst) = o2;
    } else {
        int idx = (blockIdx.x - 32768) * blockDim.x + threadIdx.x;
        int d  = idx & 127;
        int pr = (idx >> 7) & 1023;
        int bh = idx >> 17;
        int b = bh >> 4, h = bh & 15;
        const float* base = qkv + (size_t)(b * S_ + pr * 2) * E_ + 2 * D_ + h * HD_ + d;
        vh[idx] = pkh(base[E_], base[0]);
    }
}

// ---------------------------------------------------------------------------
// fp16 causal flash attention (identical to R12/R13 passing version)
// ---------------------------------------------------------------------------
#define KLDU 68
#define VLDU 136
#define KSTB (32 * KLDU * 4)
#define VSTB (16 * VLDU * 4)
#define STAGEB (KSTB + VSTB)

__global__ __launch_bounds__(128, 3) void attn_h(
    const uint32_t* __restrict__ qh, const uint32_t* __restrict__ kh,
    const uint32_t* __restrict__ vh, const float* __restrict__ m2p,
    __half* __restrict__ out)
{
    extern __shared__ __align__(16) char smc[];

    const int t    = threadIdx.x;
    const int w    = t >> 5;
    const int lane = t & 31;
    const int g    = lane >> 2;
    const int tq   = lane & 3;

    const int bh   = blockIdx.x >> 5;
    const int qblk = 31 - (blockIdx.x & 31);
    const int b    = bh >> 4;
    const int h    = bh & 15;

    const int q0  = qblk * 64;
    const int qg0 = q0 + w * 16 + g;
    const int qg1 = qg0 + 8;
    const float MB = m2p[0] - 13.0f;

    const uint32_t* qb32 = qh + (size_t)bh * S_ * 64;
    const char*     kbp  = (const char*)(kh + (size_t)bh * S_ * 64);
    const char*     vbp  = (const char*)(vh + (size_t)bh * 1024 * 128);

    unsigned qf[8][4];
#pragma unroll
    for (int ks = 0; ks < 8; ks++) {
        qf[ks][0] = qb32[(size_t)qg0 * 64 + ks * 8 + tq];
        qf[ks][1] = qb32[(size_t)qg1 * 64 + ks * 8 + tq];
        qf[ks][2] = qb32[(size_t)qg0 * 64 + ks * 8 + tq + 4];
        qf[ks][3] = qb32[(size_t)qg1 * 64 + ks * 8 + tq + 4];
    }

    float acc[16][4];
#pragma unroll
    for (int i = 0; i < 16; i++)
#pragma unroll
        for (int r = 0; r < 4; r++) acc[i][r] = 0.f;
    float l0 = 0.f, l1 = 0.f;
    const float sc2 = 0.08838834764831845f * 1.4426950408889634f;

    auto issue = [&](int j, int st) {
        char* kdst = smc + st * STAGEB;
        char* vdst = kdst + KSTB;
        const char* ksrc = kbp + (size_t)j * 32 * 256;
        const char* vsrc = vbp + (size_t)j * 16 * 512;
#pragma unroll
        for (int u = 0; u < 4; u++) {
            int c = u * 128 + t;
            int r = c >> 4, col = c & 15;
            cp_async16(kdst + r * 272 + col * 16, ksrc + r * 256 + col * 16);
        }
#pragma unroll
        for (int u = 0; u < 4; u++) {
            int c = u * 128 + t;
            int r = c >> 5, col = c & 31;
            cp_async16(vdst + r * 544 + col * 16, vsrc + r * 512 + col * 16);
        }
        cp_commit();
    };

    const int nblk = 2 * qblk + 2;
    issue(0, 0);
    issue(1, 1);

    for (int j = 0; j < nblk; j++) {
        if (j + 1 < nblk) cp_wait1(); else cp_wait0();
        __syncthreads();
        if (j + 2 < nblk) issue(j + 2, (j + 2) % 3);

        const uint32_t* cK = (const uint32_t*)(smc + (j % 3) * STAGEB);
        const uint32_t* cV = (const uint32_t*)(smc + (j % 3) * STAGEB + KSTB);
        const int k0 = j * 32;

        float sa[4][4];
#pragma unroll
        for (int nt = 0; nt < 4; nt++)
#pragma unroll
            for (int r = 0; r < 4; r++) sa[nt][r] = 0.f;
#pragma unroll
        for (int ks = 0; ks < 8; ks++) {
#pragma unroll
            for (int nt = 0; nt < 4; nt++) {
                unsigned b0 = cK[(nt * 8 + g) * KLDU + ks * 8 + tq];
                unsigned b1 = cK[(nt * 8 + g) * KLDU + ks * 8 + tq + 4];
                mma_f16(sa[nt][0], sa[nt][1], sa[nt][2], sa[nt][3],
                        qf[ks][0], qf[ks][1], qf[ks][2], qf[ks][3], b0, b1);
            }
        }

        if (k0 + 31 > q0 + w * 16) {
#pragma unroll
            for (int nt = 0; nt < 4; nt++) {
                int kva = k0 + nt * 8 + tq * 2;
                float p0 = ex2f(fmaf(sa[nt][0], sc2, -MB));
                float p1 = ex2f(fmaf(sa[nt][1], sc2, -MB));
                float p2 = ex2f(fmaf(sa[nt][2], sc2, -MB));
                float p3 = ex2f(fmaf(sa[nt][3], sc2, -MB));
                p0 = (kva     <= qg0) ? p0 : 0.f;
                p1 = (kva + 1 <= qg0) ? p1 : 0.f;
                p2 = (kva     <= qg1) ? p2 : 0.f;
                p3 = (kva + 1 <= qg1) ? p3 : 0.f;
                l0 += p0 + p1; l1 += p2 + p3;
                sa[nt][0] = p0; sa[nt][1] = p1; sa[nt][2] = p2; sa[nt][3] = p3;
            }
        } else {
#pragma unroll
            for (int nt = 0; nt < 4; nt++) {
                float p0 = ex2f(fmaf(sa[nt][0], sc2, -MB));
                float p1 = ex2f(fmaf(sa[nt][1], sc2, -MB));
                float p2 = ex2f(fmaf(sa[nt][2], sc2, -MB));
                float p3 = ex2f(fmaf(sa[nt][3], sc2, -MB));
                l0 += p0 + p1; l1 += p2 + p3;
                sa[nt][0] = p0; sa[nt][1] = p1; sa[nt][2] = p2; sa[nt][3] = p3;
            }
        }

#pragma unroll
        for (int i = 0; i < 2; i++) {
            unsigned a0 = pkh(sa[2*i][1],   sa[2*i][0]);
            unsigned a1 = pkh(sa[2*i][3],   sa[2*i][2]);
            unsigned a2 = pkh(sa[2*i+1][1], sa[2*i+1][0]);
            unsigned a3 = pkh(sa[2*i+1][3], sa[2*i+1][2]);
            const uint32_t* vr0 = &cV[(i * 8 + tq) * VLDU];
            const uint32_t* vr1 = &cV[(i * 8 + tq + 4) * VLDU];
#pragma unroll
            for (int nt = 0; nt < 16; nt++) {
                mma_f16(acc[nt][0], acc[nt][1], acc[nt][2], acc[nt][3],
                        a0, a1, a2, a3, vr0[nt * 8 + g], vr1[nt * 8 + g]);
            }
        }
    }

    l0 += __shfl_xor_sync(0xffffffffu, l0, 1);
    l0 += __shfl_xor_sync(0xffffffffu, l0, 2);
    l1 += __shfl_xor_sync(0xffffffffu, l1, 1);
    l1 += __shfl_xor_sync(0xffffffffu, l1, 2);

    float inv0 = 1.0f / l0, inv1 = 1.0f / l1;
    uint32_t* o0 = (uint32_t*)(out + (size_t)(b * S_ + qg0) * D_ + h * HD_);
    uint32_t* o1 = (uint32_t*)(out + (size_t)(b * S_ + qg1) * D_ + h * HD_);
#pragma unroll
    for (int nt = 0; nt < 16; nt++) {
        o0[nt * 4 + tq] = pkh(acc[nt][1] * inv0, acc[nt][0] * inv0);
        o1[nt * 4 + tq] = pkh(acc[nt][3] * inv1, acc[nt][2] * inv1);
    }
}

// ---------------------------------------------------------------------------
extern "C" void kernel_launch(void* const* d_in, const int* in_sizes, int n_in,
                              void* d_out, int out_size)
{
    const float* x     = (const float*)d_in[0];
    const float* w_in  = (const float*)d_in[1];
    const float* w_out = (const float*)d_in[2];
    const float* qg    = (const float*)d_in[3];
    const float* kg    = (const float*)d_in[4];
    float* out = (float*)d_out;

    float *qkv, *m2;
    __half *xh, *wih, *woh, *ath;
    uint32_t *qh, *kh, *vh;
    cudaGetSymbolAddress((void**)&qkv, g_qkv);
    cudaGetSymbolAddress((void**)&m2,  g_m2);
    cudaGetSymbolAddress((void**)&xh,  g_xh);
    cudaGetSymbolAddress((void**)&wih, g_wih);
    cudaGetSymbolAddress((void**)&woh, g_woh);
    cudaGetSymbolAddress((void**)&ath, g_ath);
    cudaGetSymbolAddress((void**)&qh,  g_qh);
    cudaGetSymbolAddress((void**)&kh,  g_kh);
    cudaGetSymbolAddress((void**)&vh,  g_vh);

    const int gsm = NSTG * STGB;         // 110592 B
    cudaFuncSetAttribute(gemm_f16, cudaFuncAttributeMaxDynamicSharedMemorySize, gsm);
    const int asm_ = 3 * STAGEB;         // 52224 B
    cudaFuncSetAttribute(attn_h, cudaFuncAttributeMaxDynamicSharedMemorySize, asm_);

    tofp16<<<1184, 256>>>(x, xh, BS_ * D_ / 4);
    tofp16<<<1184, 256>>>(w_in, wih, E_ * D_ / 4);
    gmax_kernel<<<1, 32>>>(qg, kg, m2);

    // 4th launch: profiled
    gemm_f16<<<dim3(E_ / 128, BS_ / 128), 128, gsm>>>(xh, wih, qkv, BS_, E_, D_);

    tofp16<<<1184, 256>>>(w_out, woh, D_ * D_ / 4);
    rms_vpack<<<65536, 256>>>(qkv, qg, kg, qh, kh, vh);
    attn_h<<<64 * 32, 128, asm_>>>(qh, kh, vh, m2, ath);
    gemm_f16<<<dim3(D_ / 128, BS_ / 128), 128, gsm>>>(ath, woh, out, BS_, D_, D_);
}